// round 10
// baseline (speedup 1.0000x reference)
#include <cuda_runtime.h>
#include <cuda_fp16.h>
#include <math.h>
#include <stdint.h>

// ---------------- problem constants ----------------
#define Bn    2
#define Ln    2048
#define Dn    2048
#define DINn  4096
#define Nn    128
#define Hn    64
#define Pn    64
#define Kc    4
#define CONVD 4352            // DIN + 2*G*N
#define Qn    64
#define NCn   32
#define PROJW 8512            // 2*DIN + 2*G*N + H
#define DTOFF 8448            // DIN + CONVD
#define BLn   (Bn*Ln)         // 4096
#define EPSf  1e-5f

// GEMM tiling: 128(M) x NTILE(N) block tile, BK=64, 512 threads, fp16 single-pass
#define A_CH  16384           // bytes per A chunk-tile (128 x 64 fp16, swizzled image)
#define B_CH  32768           // bytes per B chunk-tile (256 x 64 fp16, swizzled image)
#define NSTAGE 3

#define NCH1  32              // in_proj K chunks (2048/64)
#define NT1   34              // in_proj N tiles  (8704/256)
#define NCH2  64              // out_proj K chunks (4096/64)
#define MTil  32              // M tiles (4096/128)

// ---------------- scratch ----------------
__device__ float g_h[(size_t)BLn*Dn];                 // normalized input (fp32, for dt GEMM)
__device__ float g_proj[(size_t)BLn*PROJW];
__device__ float g_xbc[(size_t)BLn*CONVD];
__device__ float g_dt[(size_t)BLn*Hn];
__device__ float g_a[(size_t)BLn*Hn];
__device__ float g_acs[(size_t)BLn*Hn];
__device__ float g_csum[(size_t)Bn*Hn*NCn];
__device__ float g_states[(size_t)Bn*Hn*NCn*Pn*Nn];
__device__ float g_statein[(size_t)Bn*Hn*NCn*Pn*Nn];
__device__ float g_y[(size_t)BLn*DINn];

// fp16 tile buffers (SW128-swizzled SMEM image, chunk-tiled)
__device__ __align__(1024) unsigned char g_Af[(size_t)MTil*NCH2*A_CH];
__device__ __align__(1024) unsigned char g_Bf[(size_t)NT1*NCH1*B_CH];

// ---------------- PTX helpers ----------------
__device__ __forceinline__ uint32_t smem_u32(const void* p) {
    uint32_t a;
    asm("{ .reg .u64 t; cvta.to.shared.u64 t, %1; cvt.u32.u64 %0, t; }" : "=r"(a) : "l"(p));
    return a;
}
__device__ __forceinline__ uint32_t swz128(uint32_t o) { return o ^ ((o >> 3) & 0x70); }

#define MBAR_INIT(a, c) \
    asm volatile("mbarrier.init.shared.b64 [%0], %1;" :: "r"(a), "r"(c) : "memory")
#define MBAR_EXPECT_TX(a, b) \
    asm volatile("mbarrier.arrive.expect_tx.shared.b64 _, [%0], %1;" :: "r"(a), "r"(b) : "memory")
#define MBAR_WAIT(a, ph) do { \
    uint32_t _m = (a); uint32_t _p = (ph); uint32_t _d; \
    asm volatile("{\n\t.reg .pred p;\n\t" \
        "mbarrier.try_wait.parity.acquire.cta.shared::cta.b64 p, [%1], %2;\n\t" \
        "selp.b32 %0, 1, 0, p;\n\t}" : "=r"(_d) : "r"(_m), "r"(_p) : "memory"); \
    if (!_d) { \
        asm volatile("{\n\t.reg .pred P1;\n\t" \
            "WL_%=:\n\t" \
            "mbarrier.try_wait.parity.acquire.cta.shared::cta.b64 P1, [%0], %1, 0x989680;\n\t" \
            "@P1 bra.uni WD_%=;\n\t" \
            "bra.uni WL_%=;\n\t" \
            "WD_%=:\n\t}" :: "r"(_m), "r"(_p) : "memory"); \
    } \
} while (0)

#define BULK_LD(sa, gp, bytes, mb) \
    asm volatile("cp.async.bulk.shared::cluster.global.mbarrier::complete_tx::bytes [%0], [%1], %2, [%3];" \
        :: "r"(sa), "l"(gp), "r"(bytes), "r"(mb) : "memory")

#define LDSMX4(r, addr) \
    asm volatile("ldmatrix.sync.aligned.m8n8.x4.shared.b16 {%0,%1,%2,%3}, [%4];" \
        : "=r"((r)[0]), "=r"((r)[1]), "=r"((r)[2]), "=r"((r)[3]) : "r"(addr))

#define MMA_FP16(d, a, b0, b1) \
    asm volatile("mma.sync.aligned.m16n8k16.row.col.f32.f16.f16.f32 " \
        "{%0,%1,%2,%3}, {%4,%5,%6,%7}, {%8,%9}, {%0,%1,%2,%3};" \
        : "+f"((d)[0]), "+f"((d)[1]), "+f"((d)[2]), "+f"((d)[3]) \
        : "r"((a)[0]), "r"((a)[1]), "r"((a)[2]), "r"((a)[3]), "r"(b0), "r"(b1))

// ---------------- misc helpers ----------------
__device__ __forceinline__ float block_reduce_sum(float v) {
    __shared__ float red[32];
    int lane = threadIdx.x & 31, wid = threadIdx.x >> 5;
    #pragma unroll
    for (int o = 16; o; o >>= 1) v += __shfl_down_sync(0xffffffffu, v, o);
    if (lane == 0) red[wid] = v;
    __syncthreads();
    v = (threadIdx.x < (blockDim.x >> 5)) ? red[threadIdx.x] : 0.f;
    if (wid == 0) {
        #pragma unroll
        for (int o = 16; o; o >>= 1) v += __shfl_down_sync(0xffffffffu, v, o);
        if (lane == 0) red[0] = v;
    }
    __syncthreads();
    return red[0];
}
__device__ __forceinline__ float siluf(float x) { return x / (1.f + expf(-x)); }

__device__ __forceinline__ uint32_t pack2h(float x0, float x1) {
    __half h0 = __float2half_rn(x0);
    __half h1 = __float2half_rn(x1);
    return ((uint32_t)__half_as_ushort(h1) << 16) | __half_as_ushort(h0);
}

// ---------------- 1) resid + rmsnorm -> fp32 g_h + fp16 A tiles ----------------
__global__ __launch_bounds__(256) void k_add_rmsnorm_split(
    const float* __restrict__ hs, const float* __restrict__ res,
    const float* __restrict__ w, float* __restrict__ resid_out,
    unsigned char* __restrict__ Af) {
    size_t row = blockIdx.x;
    int t = threadIdx.x;
    const float4* ph = (const float4*)(hs + row * Dn);
    const float4* pr = (const float4*)(res + row * Dn);
    float4* po = (float4*)(resid_out + row * Dn);
    float v[8];
    float ss = 0.f;
    #pragma unroll
    for (int i = 0; i < 2; i++) {
        float4 a = ph[t * 2 + i], b = pr[t * 2 + i];
        float4 x = make_float4(a.x + b.x, a.y + b.y, a.z + b.z, a.w + b.w);
        po[t * 2 + i] = x;
        v[i * 4 + 0] = x.x; v[i * 4 + 1] = x.y; v[i * 4 + 2] = x.z; v[i * 4 + 3] = x.w;
        ss += x.x * x.x + x.y * x.y + x.z * x.z + x.w * x.w;
    }
    float tot = block_reduce_sum(ss);
    float inv = rsqrtf(tot / (float)Dn + EPSf);
    int mt = (int)(row >> 7), r = (int)(row & 127);
    size_t tb = (size_t)mt * NCH1 * A_CH;
    float4* gh = (float4*)(g_h + row * Dn);
    #pragma unroll
    for (int i = 0; i < 2; i++) {
        float4 x = make_float4(v[i*4]*inv*w[t*8+i*4], v[i*4+1]*inv*w[t*8+i*4+1],
                               v[i*4+2]*inv*w[t*8+i*4+2], v[i*4+3]*inv*w[t*8+i*4+3]);
        gh[t * 2 + i] = x;
        v[i*4] = x.x; v[i*4+1] = x.y; v[i*4+2] = x.z; v[i*4+3] = x.w;
    }
    #pragma unroll
    for (int j = 0; j < 4; j++) {
        int k = t * 8 + j * 2;
        uint32_t u = pack2h(v[j * 2], v[j * 2 + 1]);
        int kc = k >> 6, c = k & 63;
        size_t off = tb + (size_t)kc * A_CH + swz128((uint32_t)(r * 128 + c * 2));
        *(uint32_t*)(Af + off) = u;
    }
}

// ---------------- weight transpose to fp16: W[K x N] -> B tiles [nt][kc][256][64] ----------------
__global__ __launch_bounds__(256) void k_splitB(
    const float* __restrict__ W, unsigned char* __restrict__ Bf, int Nreal, int nch) {
    __shared__ float tile[64][33];
    int kb = blockIdx.y * 64;
    int n0 = blockIdx.x * 32;
    int t = threadIdx.x;
    int tx = t & 31, ty = t >> 5;
    #pragma unroll
    for (int i = 0; i < 8; i++) {
        int k = ty + i * 8;
        tile[k][tx] = W[(size_t)(kb + k) * Nreal + n0 + tx];
    }
    __syncthreads();
    int kc = kb >> 6;
    #pragma unroll
    for (int j = 0; j < 4; j++) {
        int nl = ty * 4 + j;
        int n = n0 + nl;
        uint32_t u = pack2h(tile[tx * 2][nl], tile[tx * 2 + 1][nl]);
        int nt = n >> 8, r = n & 255;
        size_t base = ((size_t)(nt * nch + kc)) * B_CH;
        size_t off = base + swz128((uint32_t)(r * 128 + tx * 4));
        *(uint32_t*)(Bf + off) = u;
    }
}

// ---------------- fp16 single-pass GEMM via mma.sync: C = A @ B^T-tiles ----------------
// Block tile 128(M) x NTILE(N), BK=64, 512 threads, 3-stage bulk-copy pipeline.
// R6-proven loop structure: wait full -> consume -> __syncthreads -> prefetch kc+2.
template <int NTILE>
__global__ __launch_bounds__(512) void gemm_mma_fp16(
    const unsigned char* __restrict__ Af, const unsigned char* __restrict__ Bf,
    float* __restrict__ C, int Nreal, int nch) {
    constexpr int BSTG = NTILE * 128;              // bytes of B per stage
    constexpr int STGB = 16384 + BSTG;             // stage bytes
    constexpr int WN = NTILE / 128;                // 16-wide B sub-tiles per warp (2 or 1)
    extern __shared__ unsigned char smg[];
    uint32_t sb = (smem_u32(smg) + 1023) & ~1023u;
    uint32_t ctrl = sb + NSTAGE * STGB;
    int t = threadIdx.x, lane = t & 31, wid = t >> 5;
    int bx = blockIdx.x, by = blockIdx.y;

    if (t == 0) { MBAR_INIT(ctrl + 0, 1); MBAR_INIT(ctrl + 8, 1); MBAR_INIT(ctrl + 16, 1); }
    __syncthreads();

    const unsigned char* Ap = Af + (size_t)by * nch * A_CH;
    const unsigned char* Bp;
    if (NTILE == 256) Bp = Bf + (size_t)bx * nch * B_CH;
    else              Bp = Bf + (size_t)(bx >> 1) * nch * B_CH + (size_t)(bx & 1) * 16384;

    int wm = wid & 1, wn = wid >> 1;          // 2 x 8 warps; warp tile 64(M) x NTILE/8(N)
    int rowA = wm * 64 + (lane & 7) + ((lane >> 3) & 1) * 8;
    int colA = ((lane >> 4) & 1) * 16;
    int rowB = wn * (NTILE / 8) + (lane & 7) + ((lane >> 4) & 1) * 8;
    int colB = ((lane >> 3) & 1) * 16;

    float acc[4][2 * WN][4];
    #pragma unroll
    for (int i = 0; i < 4; i++)
        #pragma unroll
        for (int j = 0; j < 2 * WN; j++)
            #pragma unroll
            for (int q = 0; q < 4; q++) acc[i][j][q] = 0.f;

    // prologue: load chunks 0 and 1
    if (t == 0) {
        MBAR_EXPECT_TX(ctrl + 0, STGB);
        BULK_LD(sb + 0,     Ap, A_CH, ctrl + 0);
        BULK_LD(sb + 16384, Bp, BSTG, ctrl + 0);
        if (nch > 1) {
            MBAR_EXPECT_TX(ctrl + 8, STGB);
            BULK_LD(sb + STGB + 0,     Ap + A_CH, A_CH, ctrl + 8);
            BULK_LD(sb + STGB + 16384, Bp + B_CH, BSTG, ctrl + 8);
        }
    }
    int ph[NSTAGE] = {0, 0, 0};
    for (int kc = 0; kc < nch; kc++) {
        int slot = kc % NSTAGE;
        MBAR_WAIT(ctrl + slot * 8, ph[slot]);
        ph[slot] ^= 1;
        uint32_t s = sb + slot * STGB;
        uint32_t sA = s, sB = s + 16384;
        #pragma unroll
        for (int k = 0; k < 4; k++) {
            uint32_t bh[WN][4];
            #pragma unroll
            for (int ib = 0; ib < WN; ib++) {
                uint32_t off = swz128((uint32_t)((rowB + ib * 16) * 128 + k * 32 + colB));
                LDSMX4(bh[ib], sB + off);
            }
            #pragma unroll
            for (int im = 0; im < 4; im++) {
                uint32_t ah[4];
                uint32_t off = swz128((uint32_t)((rowA + im * 16) * 128 + k * 32 + colA));
                LDSMX4(ah, sA + off);
                #pragma unroll
                for (int ib = 0; ib < WN; ib++)
                    #pragma unroll
                    for (int hf = 0; hf < 2; hf++)
                        MMA_FP16(acc[im][ib * 2 + hf], ah, bh[ib][2 * hf], bh[ib][2 * hf + 1]);
            }
        }
        __syncthreads();
        if (t == 0 && kc + 2 < nch) {
            int ns = (kc + 2) % NSTAGE;
            uint32_t d = sb + ns * STGB;
            uint32_t mb = ctrl + ns * 8;
            MBAR_EXPECT_TX(mb, STGB);
            BULK_LD(d + 0,     Ap + (size_t)(kc + 2) * A_CH, A_CH, mb);
            BULK_LD(d + 16384, Bp + (size_t)(kc + 2) * B_CH, BSTG, mb);
        }
    }

    // epilogue: direct fp32 stores
    int mBase = by * 128 + wm * 64;
    int nBase = bx * NTILE + wn * (NTILE / 8);
    #pragma unroll
    for (int im = 0; im < 4; im++) {
        #pragma unroll
        for (int in = 0; in < 2 * WN; in++) {
            int r = mBase + im * 16 + (lane >> 2);
            int c = nBase + in * 8 + (lane & 3) * 2;
            if (c < Nreal) {
                float2 v0 = make_float2(acc[im][in][0], acc[im][in][1]);
                float2 v1 = make_float2(acc[im][in][2], acc[im][in][3]);
                *(float2*)(C + (size_t)r * Nreal + c) = v0;
                *(float2*)(C + (size_t)(r + 8) * Nreal + c) = v1;
            }
        }
    }
}

// ---------------- exact fp32 skinny GEMM for dt columns + softplus ----------------
__global__ __launch_bounds__(256) void k_dtproj(
    const float* __restrict__ ipw, const float* __restrict__ dtb,
    const float* __restrict__ alog) {
    __shared__ float sh[64][68];   // [kk][m]
    __shared__ float sw[64][68];   // [kk][h]
    int m0 = blockIdx.x * 64;
    int t = threadIdx.x;
    int tm = t >> 4, tn = t & 15;
    float acc[4][4];
    #pragma unroll
    for (int i = 0; i < 4; i++)
        #pragma unroll
        for (int j = 0; j < 4; j++) acc[i][j] = 0.f;

    for (int kb = 0; kb < Dn; kb += 64) {
        #pragma unroll
        for (int i = 0; i < 16; i++) {
            int idx = t + i * 256;
            int m = idx >> 6, kk = idx & 63;
            sh[kk][m] = g_h[(size_t)(m0 + m) * Dn + kb + kk];
        }
        #pragma unroll
        for (int i = 0; i < 16; i++) {
            int idx = t + i * 256;
            int kk = idx >> 6, h = idx & 63;
            sw[kk][h] = ipw[(size_t)(kb + kk) * PROJW + DTOFF + h];
        }
        __syncthreads();
        #pragma unroll 8
        for (int kk = 0; kk < 64; kk++) {
            float4 ar = *(const float4*)&sh[kk][tm * 4];
            float4 br = *(const float4*)&sw[kk][tn * 4];
            float a4[4] = {ar.x, ar.y, ar.z, ar.w};
            float b4[4] = {br.x, br.y, br.z, br.w};
            #pragma unroll
            for (int i = 0; i < 4; i++)
                #pragma unroll
                for (int j = 0; j < 4; j++) acc[i][j] = fmaf(a4[i], b4[j], acc[i][j]);
        }
        __syncthreads();
    }
    #pragma unroll
    for (int i = 0; i < 4; i++) {
        int m = m0 + tm * 4 + i;
        #pragma unroll
        for (int j = 0; j < 4; j++) {
            int h = tn * 4 + j;
            float x = acc[i][j] + dtb[h];
            float sp = (x > 20.f) ? x : log1pf(expf(x));
            g_dt[(size_t)m * Hn + h] = sp;
            g_a[(size_t)m * Hn + h] = -expf(alog[h]) * sp;
        }
    }
}

// ---------------- 3) causal depthwise conv, sliding window ----------------
__global__ __launch_bounds__(256) void k_conv2(
    const float* __restrict__ cw, const float* __restrict__ cb) {
    int bid = blockIdx.x;
    int c = (bid % 17) * 256 + threadIdx.x;
    int lblk = (bid / 17) & 127;
    int b = bid / (17 * 128);
    int l0 = lblk * 16;
    float w0 = cw[c * 4 + 0], w1 = cw[c * 4 + 1], w2 = cw[c * 4 + 2], w3 = cw[c * 4 + 3];
    float bias = cb[c];
    float x[19];
    #pragma unroll
    for (int i = 0; i < 19; i++) {
        int ls = l0 - 3 + i;
        x[i] = (ls >= 0) ? g_proj[((size_t)(b * Ln + ls)) * PROJW + DINn + c] : 0.f;
    }
    #pragma unroll
    for (int j = 0; j < 16; j++) {
        float acc = fmaf(w0, x[j], fmaf(w1, x[j + 1], fmaf(w2, x[j + 2], fmaf(w3, x[j + 3], bias))));
        g_xbc[((size_t)(b * Ln + l0 + j)) * CONVD + c] = siluf(acc);
    }
}

// ---------------- 5) per-chunk: cumsum, Y_diag + D*xs, local states ----------------
__global__ __launch_bounds__(256) void k_chunk(const float* __restrict__ dskip) {
    extern __shared__ float sm[];
    float* Bsm = sm;
    float* Csm = Bsm + 64 * 129;
    float* Xd  = Csm + 64 * 129;
    float* Ms  = Xd + 64 * 65;
    float* Acs = Ms + 64 * 65;
    float* Dec = Acs + 64;

    int c = blockIdx.x, h = blockIdx.y, b = blockIdx.z;
    int t = threadIdx.x;
    size_t rowbase = ((size_t)(b * Ln + c * Qn)) * CONVD;

    for (int i = t; i < Qn * Nn; i += 256) {
        int s = i >> 7, n = i & 127;
        size_t g = rowbase + (size_t)s * CONVD + DINn;
        Bsm[s * 129 + n] = g_xbc[g + n];
        Csm[s * 129 + n] = g_xbc[g + Nn + n];
    }
    if (t < Qn) Acs[t] = g_a[(size_t)(b * Ln + c * Qn + t) * Hn + h];
    __syncthreads();
    if (t == 0) {
        float r = 0.f;
        for (int i = 0; i < Qn; i++) { r += Acs[i]; Acs[i] = r; }
    }
    __syncthreads();
    if (t < Qn) {
        float aq = Acs[t];
        Dec[t] = expf(Acs[Qn - 1] - aq);
        g_acs[(size_t)(b * Ln + c * Qn + t) * Hn + h] = aq;
        if (t == Qn - 1) g_csum[(size_t)(b * Hn + h) * NCn + c] = aq;
    }
    for (int i = t; i < Qn * Pn; i += 256) {
        int s = i >> 6, p = i & 63;
        float xs = g_xbc[rowbase + (size_t)s * CONVD + h * Pn + p];
        Xd[s * 65 + p] = xs * g_dt[(size_t)(b * Ln + c * Qn + s) * Hn + h];
    }
    __syncthreads();

    {
        int qb = t >> 4, sbq = t & 15;
        int q0 = qb * 4, s0 = sbq * 4;
        float m4[4][4];
        #pragma unroll
        for (int i = 0; i < 4; i++)
            #pragma unroll
            for (int j = 0; j < 4; j++) m4[i][j] = 0.f;
        if (s0 <= q0 + 3) {
            for (int n = 0; n < Nn; n++) {
                float cq[4], bs[4];
                #pragma unroll
                for (int i = 0; i < 4; i++) cq[i] = Csm[(q0 + i) * 129 + n];
                #pragma unroll
                for (int j = 0; j < 4; j++) bs[j] = Bsm[(s0 + j) * 129 + n];
                #pragma unroll
                for (int i = 0; i < 4; i++)
                    #pragma unroll
                    for (int j = 0; j < 4; j++) m4[i][j] = fmaf(cq[i], bs[j], m4[i][j]);
            }
        }
        #pragma unroll
        for (int i = 0; i < 4; i++)
            #pragma unroll
            for (int j = 0; j < 4; j++) {
                int q = q0 + i, s = s0 + j;
                Ms[q * 65 + s] = (s <= q) ? m4[i][j] * expf(Acs[q] - Acs[s]) : 0.f;
            }
    }
    __syncthreads();

    {
        int qb = t >> 4, pb = t & 15;
        int q0 = qb * 4, p0 = pb * 4;
        float y4[4][4];
        #pragma unroll
        for (int i = 0; i < 4; i++)
            #pragma unroll
            for (int j = 0; j < 4; j++) y4[i][j] = 0.f;
        int smax = q0 + 3;
        for (int s = 0; s <= smax; s++) {
            float mv[4], xv[4];
            #pragma unroll
            for (int i = 0; i < 4; i++) mv[i] = Ms[(q0 + i) * 65 + s];
            #pragma unroll
            for (int j = 0; j < 4; j++) xv[j] = Xd[s * 65 + p0 + j];
            #pragma unroll
            for (int i = 0; i < 4; i++)
                #pragma unroll
                for (int j = 0; j < 4; j++) y4[i][j] = fmaf(mv[i], xv[j], y4[i][j]);
        }
        float dsk = dskip[h];
        #pragma unroll
        for (int i = 0; i < 4; i++) {
            int q = q0 + i;
            #pragma unroll
            for (int j = 0; j < 4; j++) {
                int p = p0 + j;
                float xs = g_xbc[rowbase + (size_t)q * CONVD + h * Pn + p];
                g_y[((size_t)(b * Ln + c * Qn + q) * Hn + h) * Pn + p] =
                    y4[i][j] + dsk * xs;
            }
        }
    }

    {
        int pb = t >> 4, nb2 = t & 15;
        int p0 = pb * 4, n0 = nb2 * 8;
        float st[4][8];
        #pragma unroll
        for (int i = 0; i < 4; i++)
            #pragma unroll
            for (int j = 0; j < 8; j++) st[i][j] = 0.f;
        for (int q = 0; q < Qn; q++) {
            float d = Dec[q];
            float xv[4], bv[8];
            #pragma unroll
            for (int i = 0; i < 4; i++) xv[i] = Xd[q * 65 + p0 + i] * d;
            #pragma unroll
            for (int j = 0; j < 8; j++) bv[j] = Bsm[q * 129 + n0 + j];
            #pragma unroll
            for (int i = 0; i < 4; i++)
                #pragma unroll
                for (int j = 0; j < 8; j++) st[i][j] = fmaf(xv[i], bv[j], st[i][j]);
        }
        size_t base = ((size_t)(b * Hn + h) * NCn + c) * (Pn * Nn);
        #pragma unroll
        for (int i = 0; i < 4; i++)
            #pragma unroll
            for (int j = 0; j < 8; j++)
                g_states[base + (size_t)(p0 + i) * Nn + n0 + j] = st[i][j];
    }
}

// ---------------- 6) chunk-level scan, 8-way split over state elements ----------------
__global__ __launch_bounds__(256) void k_scan() {
    int bh = blockIdx.x;
    int e0 = blockIdx.y * 1024 + threadIdx.x;
    float S[4];
    #pragma unroll
    for (int k = 0; k < 4; k++) S[k] = 0.f;
    for (int c = 0; c < NCn; c++) {
        size_t base = ((size_t)bh * NCn + c) * (Pn * Nn);
        #pragma unroll
        for (int k = 0; k < 4; k++) g_statein[base + e0 + k * 256] = S[k];
        float f = expf(g_csum[(size_t)bh * NCn + c]);
        #pragma unroll
        for (int k = 0; k < 4; k++)
            S[k] = fmaf(f, S[k], g_states[base + e0 + k * 256]);
    }
}

// ---------------- 7) Y_off ----------------
__global__ __launch_bounds__(256) void k_yoff() {
    extern __shared__ float sm[];
    float* Ss  = sm;
    float* Csm = Ss + 64 * 129;
    float* Eq  = Csm + 64 * 129;

    int c = blockIdx.x, h = blockIdx.y, b = blockIdx.z;
    int t = threadIdx.x;
    size_t rowbase = ((size_t)(b * Ln + c * Qn)) * CONVD;
    size_t sbase = ((size_t)(b * Hn + h) * NCn + c) * (Pn * Nn);

    for (int i = t; i < Pn * Nn; i += 256) {
        int p = i >> 7, n = i & 127;
        Ss[p * 129 + n] = g_statein[sbase + i];
    }
    for (int i = t; i < Qn * Nn; i += 256) {
        int q = i >> 7, n = i & 127;
        Csm[q * 129 + n] = g_xbc[rowbase + (size_t)q * CONVD + DINn + Nn + n];
    }
    if (t < Qn)
        Eq[t] = expf(g_acs[(size_t)(b * Ln + c * Qn + t) * Hn + h]);
    __syncthreads();

    int qb = t >> 4, pb = t & 15;
    int q0 = qb * 4, p0 = pb * 4;
    float acc[4][4];
    #pragma unroll
    for (int i = 0; i < 4; i++)
        #pragma unroll
        for (int j = 0; j < 4; j++) acc[i][j] = 0.f;
    for (int n = 0; n < Nn; n++) {
        float cq[4], sp[4];
        #pragma unroll
        for (int i = 0; i < 4; i++) cq[i] = Csm[(q0 + i) * 129 + n];
        #pragma unroll
        for (int j = 0; j < 4; j++) sp[j] = Ss[(p0 + j) * 129 + n];
        #pragma unroll
        for (int i = 0; i < 4; i++)
            #pragma unroll
            for (int j = 0; j < 4; j++) acc[i][j] = fmaf(cq[i], sp[j], acc[i][j]);
    }
    #pragma unroll
    for (int i = 0; i < 4; i++) {
        int q = q0 + i;
        float e = Eq[q];
        #pragma unroll
        for (int j = 0; j < 4; j++) {
            int p = p0 + j;
            size_t yi = ((size_t)(b * Ln + c * Qn + q) * Hn + h) * Pn + p;
            g_y[yi] += e * acc[i][j];
        }
    }
}

// ---------------- 8) gated rmsnorm -> fp16 A tiles (K=4096, nch=64) ----------------
__global__ __launch_bounds__(256) void k_gatenorm_split(
    const float* __restrict__ gw, unsigned char* __restrict__ Af) {
    size_t row = blockIdx.x;
    int t = threadIdx.x;
    const float4* py = (const float4*)(g_y + row * DINn);
    const float4* pz = (const float4*)(g_proj + row * PROJW);
    float v[16];
    float ss = 0.f;
    #pragma unroll
    for (int i = 0; i < 4; i++) {
        float4 y4 = py[t * 4 + i];
        float4 z4 = pz[t * 4 + i];
        float x0 = y4.x * siluf(z4.x);
        float x1 = y4.y * siluf(z4.y);
        float x2 = y4.z * siluf(z4.z);
        float x3 = y4.w * siluf(z4.w);
        v[i * 4 + 0] = x0; v[i * 4 + 1] = x1; v[i * 4 + 2] = x2; v[i * 4 + 3] = x3;
        ss += x0 * x0 + x1 * x1 + x2 * x2 + x3 * x3;
    }
    float tot = block_reduce_sum(ss);
    float inv = rsqrtf(tot / (float)DINn + EPSf);
    int mt = (int)(row >> 7), r = (int)(row & 127);
    size_t tb = (size_t)mt * NCH2 * A_CH;
    #pragma unroll
    for (int j = 0; j < 8; j++) {
        int k = t * 16 + j * 2;
        uint32_t u = pack2h(v[j * 2] * inv * gw[k], v[j * 2 + 1] * inv * gw[k + 1]);
        int kc = k >> 6, cc = k & 63;
        size_t off = tb + (size_t)kc * A_CH + swz128((uint32_t)(r * 128 + cc * 2));
        *(uint32_t*)(Af + off) = u;
    }
}

// ---------------- launch ----------------
extern "C" void kernel_launch(void* const* d_in, const int* in_sizes, int n_in,
                              void* d_out, int out_size) {
    const float* hs   = (const float*)d_in[0];
    const float* res  = (const float*)d_in[1];
    const float* nw   = (const float*)d_in[2];
    const float* ipw  = (const float*)d_in[3];
    const float* cw   = (const float*)d_in[4];
    const float* cb   = (const float*)d_in[5];
    const float* alog = (const float*)d_in[6];
    const float* dtb  = (const float*)d_in[7];
    const float* dsk  = (const float*)d_in[8];
    const float* gnw  = (const float*)d_in[9];
    const float* opw  = (const float*)d_in[10];
    float* out = (float*)d_out;

    void *pproj, *pAf, *pBf, *pyfb;
    cudaGetSymbolAddress(&pproj, g_proj);
    cudaGetSymbolAddress(&pAf, g_Af);
    cudaGetSymbolAddress(&pBf, g_Bf);
    cudaGetSymbolAddress(&pyfb, g_y);

    float* resid_ptr = ((size_t)out_size >= 2ull * BLn * Dn)
                           ? out + (size_t)BLn * Dn
                           : (float*)pyfb;

    const int SMEM_CHUNK = (2 * 64 * 129 + 2 * 64 * 65 + 128) * 4;
    const int SMEM_YOFF  = (2 * 64 * 129 + 64) * 4;
    const int SMEM_G256  = 1024 + NSTAGE * (16384 + 32768) + 64;
    const int SMEM_G128  = 1024 + NSTAGE * (16384 + 16384) + 64;
    cudaFuncSetAttribute(k_chunk, cudaFuncAttributeMaxDynamicSharedMemorySize, SMEM_CHUNK);
    cudaFuncSetAttribute(k_yoff,  cudaFuncAttributeMaxDynamicSharedMemorySize, SMEM_YOFF);
    cudaFuncSetAttribute(gemm_mma_fp16<256>, cudaFuncAttributeMaxDynamicSharedMemorySize, SMEM_G256);
    cudaFuncSetAttribute(gemm_mma_fp16<128>, cudaFuncAttributeMaxDynamicSharedMemorySize, SMEM_G128);

    // 1) resid + rmsnorm -> fp32 g_h + fp16 A tiles
    k_add_rmsnorm_split<<<BLn, 256>>>(hs, res, nw, resid_ptr, (unsigned char*)pAf);

    // 1b) exact fp32 dt projection + softplus (precision-critical path)
    k_dtproj<<<BLn / 64, 256>>>(ipw, dtb, alog);

    // 2a) transpose in_proj_w -> fp16 B tiles
    {
        dim3 grid(PROJW / 32, Dn / 64);
        k_splitB<<<grid, 256>>>(ipw, (unsigned char*)pBf, PROJW, NCH1);
    }
    // 2b) proj = h @ in_proj_w  (fp16 HMMA, 256-wide tiles)
    {
        dim3 grid(NT1, MTil);
        gemm_mma_fp16<256><<<grid, 512, SMEM_G256>>>(
            (const unsigned char*)pAf, (const unsigned char*)pBf,
            (float*)pproj, PROJW, NCH1);
    }

    // 3) conv + silu (sliding window)
    k_conv2<<<Bn * 128 * 17, 256>>>(cw, cb);

    // 5) chunk kernel
    {
        dim3 grid(NCn, Hn, Bn);
        k_chunk<<<grid, 256, SMEM_CHUNK>>>(dsk);
    }

    // 6) inter-chunk scan (8-way split)
    {
        dim3 grid(Bn * Hn, 8);
        k_scan<<<grid, 256>>>();
    }

    // 7) Y_off
    {
        dim3 grid(NCn, Hn, Bn);
        k_yoff<<<grid, 256, SMEM_YOFF>>>();
    }

    // 8) gated rmsnorm -> fp16 A tiles (K=4096)
    k_gatenorm_split<<<BLn, 256>>>(gnw, (unsigned char*)pAf);

    // 9a) transpose out_proj_w -> fp16 B tiles
    {
        dim3 grid(Dn / 32, DINn / 64);
        k_splitB<<<grid, 256>>>(opw, (unsigned char*)pBf, Dn, NCH2);
    }
    // 9b) out = yg @ out_proj_w  (128-wide tiles -> 512 CTAs for balance)
    {
        dim3 grid(Dn / 128, MTil);
        gemm_mma_fp16<128><<<grid, 512, SMEM_G128>>>(
            (const unsigned char*)pAf, (const unsigned char*)pBf,
            out, Dn, NCH2);
    }
}

// round 11
// speedup vs baseline: 1.5673x; 1.5673x over previous
#include <cuda_runtime.h>
#include <cuda_fp16.h>
#include <math.h>
#include <stdint.h>

// ---------------- problem constants ----------------
#define Bn    2
#define Ln    2048
#define Dn    2048
#define DINn  4096
#define Nn    128
#define Hn    64
#define Pn    64
#define Kc    4
#define CONVD 4352            // DIN + 2*G*N
#define Qn    64
#define NCn   32
#define PROJW 8512            // 2*DIN + 2*G*N + H
#define DTOFF 8448            // DIN + CONVD
#define BLn   (Bn*Ln)         // 4096
#define EPSf  1e-5f

// GEMM tiling: 128(M) x 256(N) block tile, BK=64, 512 threads, fp16 single-pass
#define A_CH  16384           // bytes per A chunk-tile (128 x 64 fp16, swizzled image)
#define B_CH  32768           // bytes per B chunk-tile (256 x 64 fp16, swizzled image)
#define NSTAGE 4

#define NCH1  32              // in_proj K chunks (2048/64)
#define NT1   34              // in_proj N tiles  (8704/256)
#define NCH2  64              // out_proj K chunks (4096/64)
#define MTil  32              // M tiles (4096/128)

// ---------------- scratch ----------------
__device__ float g_h[(size_t)BLn*Dn];                 // normalized input (fp32, for dt GEMM)
__device__ float g_proj[(size_t)BLn*PROJW];
__device__ float g_xbc[(size_t)BLn*CONVD];
__device__ float g_dt[(size_t)BLn*Hn];
__device__ float g_a[(size_t)BLn*Hn];
__device__ float g_acs[(size_t)BLn*Hn];
__device__ float g_csum[(size_t)Bn*Hn*NCn];
__device__ float g_states[(size_t)Bn*Hn*NCn*Pn*Nn];
__device__ float g_statein[(size_t)Bn*Hn*NCn*Pn*Nn];
__device__ float g_y[(size_t)BLn*DINn];

// fp16 tile buffers (SW128-swizzled SMEM image, chunk-tiled)
__device__ __align__(1024) unsigned char g_Af[(size_t)MTil*NCH2*A_CH];
__device__ __align__(1024) unsigned char g_Bf[(size_t)NT1*NCH1*B_CH];

// ---------------- PTX helpers ----------------
__device__ __forceinline__ uint32_t smem_u32(const void* p) {
    uint32_t a;
    asm("{ .reg .u64 t; cvta.to.shared.u64 t, %1; cvt.u32.u64 %0, t; }" : "=r"(a) : "l"(p));
    return a;
}
__device__ __forceinline__ uint32_t swz128(uint32_t o) { return o ^ ((o >> 3) & 0x70); }

#define MBAR_INIT(a, c) \
    asm volatile("mbarrier.init.shared.b64 [%0], %1;" :: "r"(a), "r"(c) : "memory")
#define MBAR_EXPECT_TX(a, b) \
    asm volatile("mbarrier.arrive.expect_tx.shared.b64 _, [%0], %1;" :: "r"(a), "r"(b) : "memory")
#define MBAR_WAIT(a, ph) do { \
    uint32_t _m = (a); uint32_t _p = (ph); uint32_t _d; \
    asm volatile("{\n\t.reg .pred p;\n\t" \
        "mbarrier.try_wait.parity.acquire.cta.shared::cta.b64 p, [%1], %2;\n\t" \
        "selp.b32 %0, 1, 0, p;\n\t}" : "=r"(_d) : "r"(_m), "r"(_p) : "memory"); \
    if (!_d) { \
        asm volatile("{\n\t.reg .pred P1;\n\t" \
            "WL_%=:\n\t" \
            "mbarrier.try_wait.parity.acquire.cta.shared::cta.b64 P1, [%0], %1, 0x989680;\n\t" \
            "@P1 bra.uni WD_%=;\n\t" \
            "bra.uni WL_%=;\n\t" \
            "WD_%=:\n\t}" :: "r"(_m), "r"(_p) : "memory"); \
    } \
} while (0)

#define BULK_LD(sa, gp, bytes, mb) \
    asm volatile("cp.async.bulk.shared::cluster.global.mbarrier::complete_tx::bytes [%0], [%1], %2, [%3];" \
        :: "r"(sa), "l"(gp), "r"(bytes), "r"(mb) : "memory")

#define LDSMX4(r, addr) \
    asm volatile("ldmatrix.sync.aligned.m8n8.x4.shared.b16 {%0,%1,%2,%3}, [%4];" \
        : "=r"((r)[0]), "=r"((r)[1]), "=r"((r)[2]), "=r"((r)[3]) : "r"(addr))

#define MMA_FP16(d, a, b0, b1) \
    asm volatile("mma.sync.aligned.m16n8k16.row.col.f32.f16.f16.f32 " \
        "{%0,%1,%2,%3}, {%4,%5,%6,%7}, {%8,%9}, {%0,%1,%2,%3};" \
        : "+f"((d)[0]), "+f"((d)[1]), "+f"((d)[2]), "+f"((d)[3]) \
        : "r"((a)[0]), "r"((a)[1]), "r"((a)[2]), "r"((a)[3]), "r"(b0), "r"(b1))

// ---------------- misc helpers ----------------
__device__ __forceinline__ float block_reduce_sum(float v) {
    __shared__ float red[32];
    int lane = threadIdx.x & 31, wid = threadIdx.x >> 5;
    #pragma unroll
    for (int o = 16; o; o >>= 1) v += __shfl_down_sync(0xffffffffu, v, o);
    if (lane == 0) red[wid] = v;
    __syncthreads();
    v = (threadIdx.x < (blockDim.x >> 5)) ? red[threadIdx.x] : 0.f;
    if (wid == 0) {
        #pragma unroll
        for (int o = 16; o; o >>= 1) v += __shfl_down_sync(0xffffffffu, v, o);
        if (lane == 0) red[0] = v;
    }
    __syncthreads();
    return red[0];
}
__device__ __forceinline__ float siluf(float x) { return x / (1.f + expf(-x)); }

__device__ __forceinline__ uint32_t pack2h(float x0, float x1) {
    __half h0 = __float2half_rn(x0);
    __half h1 = __float2half_rn(x1);
    return ((uint32_t)__half_as_ushort(h1) << 16) | __half_as_ushort(h0);
}

// ---------------- 1) resid + rmsnorm -> fp32 g_h + fp16 A tiles ----------------
__global__ __launch_bounds__(256) void k_add_rmsnorm_split(
    const float* __restrict__ hs, const float* __restrict__ res,
    const float* __restrict__ w, float* __restrict__ resid_out,
    unsigned char* __restrict__ Af) {
    size_t row = blockIdx.x;
    int t = threadIdx.x;
    const float4* ph = (const float4*)(hs + row * Dn);
    const float4* pr = (const float4*)(res + row * Dn);
    float4* po = (float4*)(resid_out + row * Dn);
    float v[8];
    float ss = 0.f;
    #pragma unroll
    for (int i = 0; i < 2; i++) {
        float4 a = ph[t * 2 + i], b = pr[t * 2 + i];
        float4 x = make_float4(a.x + b.x, a.y + b.y, a.z + b.z, a.w + b.w);
        po[t * 2 + i] = x;
        v[i * 4 + 0] = x.x; v[i * 4 + 1] = x.y; v[i * 4 + 2] = x.z; v[i * 4 + 3] = x.w;
        ss += x.x * x.x + x.y * x.y + x.z * x.z + x.w * x.w;
    }
    float tot = block_reduce_sum(ss);
    float inv = rsqrtf(tot / (float)Dn + EPSf);
    int mt = (int)(row >> 7), r = (int)(row & 127);
    size_t tb = (size_t)mt * NCH1 * A_CH;
    float4* gh = (float4*)(g_h + row * Dn);
    #pragma unroll
    for (int i = 0; i < 2; i++) {
        float4 x = make_float4(v[i*4]*inv*w[t*8+i*4], v[i*4+1]*inv*w[t*8+i*4+1],
                               v[i*4+2]*inv*w[t*8+i*4+2], v[i*4+3]*inv*w[t*8+i*4+3]);
        gh[t * 2 + i] = x;
        v[i*4] = x.x; v[i*4+1] = x.y; v[i*4+2] = x.z; v[i*4+3] = x.w;
    }
    #pragma unroll
    for (int j = 0; j < 4; j++) {
        int k = t * 8 + j * 2;
        uint32_t u = pack2h(v[j * 2], v[j * 2 + 1]);
        int kc = k >> 6, c = k & 63;
        size_t off = tb + (size_t)kc * A_CH + swz128((uint32_t)(r * 128 + c * 2));
        *(uint32_t*)(Af + off) = u;
    }
}

// ---------------- weight transpose to fp16: W[K x N] -> B tiles [nt][kc][256][64] ----------------
__global__ __launch_bounds__(256) void k_splitB(
    const float* __restrict__ W, unsigned char* __restrict__ Bf, int Nreal, int nch) {
    __shared__ float tile[64][33];
    int kb = blockIdx.y * 64;
    int n0 = blockIdx.x * 32;
    int t = threadIdx.x;
    int tx = t & 31, ty = t >> 5;
    #pragma unroll
    for (int i = 0; i < 8; i++) {
        int k = ty + i * 8;
        tile[k][tx] = W[(size_t)(kb + k) * Nreal + n0 + tx];
    }
    __syncthreads();
    int kc = kb >> 6;
    #pragma unroll
    for (int j = 0; j < 4; j++) {
        int nl = ty * 4 + j;
        int n = n0 + nl;
        uint32_t u = pack2h(tile[tx * 2][nl], tile[tx * 2 + 1][nl]);
        int nt = n >> 8, r = n & 255;
        size_t base = ((size_t)(nt * nch + kc)) * B_CH;
        size_t off = base + swz128((uint32_t)(r * 128 + tx * 4));
        *(uint32_t*)(Bf + off) = u;
    }
}

// ---------------- fp16 single-pass GEMM via mma.sync: C = A @ B^T-tiles ----------------
// Block tile 128(M) x 256(N), BK=64, 512 threads, 4-stage bulk-copy pipeline,
// prefetch distance 3. R6-proven loop: wait full -> consume -> __syncthreads -> prefetch.
__global__ __launch_bounds__(512) void gemm_mma_fp16(
    const unsigned char* __restrict__ Af, const unsigned char* __restrict__ Bf,
    float* __restrict__ C, int Nreal, int nch) {
    constexpr int STGB = 16384 + 32768;            // stage bytes (A + B)
    extern __shared__ unsigned char smg[];
    uint32_t sb = (smem_u32(smg) + 1023) & ~1023u;
    uint32_t ctrl = sb + NSTAGE * STGB;
    int t = threadIdx.x, lane = t & 31, wid = t >> 5;
    int bx = blockIdx.x, by = blockIdx.y;

    if (t == 0) {
        MBAR_INIT(ctrl + 0, 1); MBAR_INIT(ctrl + 8, 1);
        MBAR_INIT(ctrl + 16, 1); MBAR_INIT(ctrl + 24, 1);
    }
    __syncthreads();

    const unsigned char* Ap = Af + (size_t)by * nch * A_CH;
    const unsigned char* Bp = Bf + (size_t)bx * nch * B_CH;

    int wm = wid & 1, wn = wid >> 1;          // 2 x 8 warps; warp tile 64(M) x 32(N)
    int rowA = wm * 64 + (lane & 7) + ((lane >> 3) & 1) * 8;
    int colA = ((lane >> 4) & 1) * 16;
    int rowB = wn * 32 + (lane & 7) + ((lane >> 4) & 1) * 8;
    int colB = ((lane >> 3) & 1) * 16;

    float acc[4][4][4];
    #pragma unroll
    for (int i = 0; i < 4; i++)
        #pragma unroll
        for (int j = 0; j < 4; j++)
            #pragma unroll
            for (int q = 0; q < 4; q++) acc[i][j][q] = 0.f;

    // prologue: load chunks 0..2 into slots 0..2
    if (t == 0) {
        #pragma unroll
        for (int pc = 0; pc < 3; pc++) {
            if (pc < nch) {
                MBAR_EXPECT_TX(ctrl + pc * 8, STGB);
                BULK_LD(sb + pc * STGB + 0,     Ap + (size_t)pc * A_CH, A_CH, ctrl + pc * 8);
                BULK_LD(sb + pc * STGB + 16384, Bp + (size_t)pc * B_CH, B_CH, ctrl + pc * 8);
            }
        }
    }
    int ph[NSTAGE] = {0, 0, 0, 0};
    for (int kc = 0; kc < nch; kc++) {
        int slot = kc % NSTAGE;
        MBAR_WAIT(ctrl + slot * 8, ph[slot]);
        ph[slot] ^= 1;
        uint32_t s = sb + slot * STGB;
        uint32_t sA = s, sB = s + 16384;
        #pragma unroll
        for (int k = 0; k < 4; k++) {
            uint32_t bh[2][4];
            #pragma unroll
            for (int ib = 0; ib < 2; ib++) {
                uint32_t off = swz128((uint32_t)((rowB + ib * 16) * 128 + k * 32 + colB));
                LDSMX4(bh[ib], sB + off);
            }
            #pragma unroll
            for (int im = 0; im < 4; im++) {
                uint32_t ah[4];
                uint32_t off = swz128((uint32_t)((rowA + im * 16) * 128 + k * 32 + colA));
                LDSMX4(ah, sA + off);
                #pragma unroll
                for (int ib = 0; ib < 2; ib++)
                    #pragma unroll
                    for (int hf = 0; hf < 2; hf++)
                        MMA_FP16(acc[im][ib * 2 + hf], ah, bh[ib][2 * hf], bh[ib][2 * hf + 1]);
            }
        }
        __syncthreads();
        if (t == 0 && kc + 3 < nch) {
            int ns = (kc + 3) % NSTAGE;   // slot ns == (kc)%4 + 3 mod 4; consumed at chunk kc? No:
            // slot ns was last consumed at chunk kc+3-NSTAGE = kc-1 (all warps past sync of kc-1 and kc)
            uint32_t d = sb + ns * STGB;
            uint32_t mb = ctrl + ns * 8;
            MBAR_EXPECT_TX(mb, STGB);
            BULK_LD(d + 0,     Ap + (size_t)(kc + 3) * A_CH, A_CH, mb);
            BULK_LD(d + 16384, Bp + (size_t)(kc + 3) * B_CH, B_CH, mb);
        }
    }

    // epilogue: direct fp32 stores
    int mBase = by * 128 + wm * 64;
    int nBase = bx * 256 + wn * 32;
    #pragma unroll
    for (int im = 0; im < 4; im++) {
        #pragma unroll
        for (int in = 0; in < 4; in++) {
            int r = mBase + im * 16 + (lane >> 2);
            int c = nBase + in * 8 + (lane & 3) * 2;
            if (c < Nreal) {
                float2 v0 = make_float2(acc[im][in][0], acc[im][in][1]);
                float2 v1 = make_float2(acc[im][in][2], acc[im][in][3]);
                *(float2*)(C + (size_t)r * Nreal + c) = v0;
                *(float2*)(C + (size_t)(r + 8) * Nreal + c) = v1;
            }
        }
    }
}

// ---------------- exact fp32 skinny GEMM for dt columns + softplus ----------------
__global__ __launch_bounds__(256) void k_dtproj(
    const float* __restrict__ ipw, const float* __restrict__ dtb,
    const float* __restrict__ alog) {
    __shared__ float sh[64][68];   // [kk][m]
    __shared__ float sw[64][68];   // [kk][h]
    int m0 = blockIdx.x * 64;
    int t = threadIdx.x;
    int tm = t >> 4, tn = t & 15;
    float acc[4][4];
    #pragma unroll
    for (int i = 0; i < 4; i++)
        #pragma unroll
        for (int j = 0; j < 4; j++) acc[i][j] = 0.f;

    for (int kb = 0; kb < Dn; kb += 64) {
        #pragma unroll
        for (int i = 0; i < 16; i++) {
            int idx = t + i * 256;
            int m = idx >> 6, kk = idx & 63;
            sh[kk][m] = g_h[(size_t)(m0 + m) * Dn + kb + kk];
        }
        #pragma unroll
        for (int i = 0; i < 16; i++) {
            int idx = t + i * 256;
            int kk = idx >> 6, h = idx & 63;
            sw[kk][h] = ipw[(size_t)(kb + kk) * PROJW + DTOFF + h];
        }
        __syncthreads();
        #pragma unroll 8
        for (int kk = 0; kk < 64; kk++) {
            float4 ar = *(const float4*)&sh[kk][tm * 4];
            float4 br = *(const float4*)&sw[kk][tn * 4];
            float a4[4] = {ar.x, ar.y, ar.z, ar.w};
            float b4[4] = {br.x, br.y, br.z, br.w};
            #pragma unroll
            for (int i = 0; i < 4; i++)
                #pragma unroll
                for (int j = 0; j < 4; j++) acc[i][j] = fmaf(a4[i], b4[j], acc[i][j]);
        }
        __syncthreads();
    }
    #pragma unroll
    for (int i = 0; i < 4; i++) {
        int m = m0 + tm * 4 + i;
        #pragma unroll
        for (int j = 0; j < 4; j++) {
            int h = tn * 4 + j;
            float x = acc[i][j] + dtb[h];
            float sp = (x > 20.f) ? x : log1pf(expf(x));
            g_dt[(size_t)m * Hn + h] = sp;
            g_a[(size_t)m * Hn + h] = -expf(alog[h]) * sp;
        }
    }
}

// ---------------- 3) causal depthwise conv, sliding window ----------------
__global__ __launch_bounds__(256) void k_conv2(
    const float* __restrict__ cw, const float* __restrict__ cb) {
    int bid = blockIdx.x;
    int c = (bid % 17) * 256 + threadIdx.x;
    int lblk = (bid / 17) & 127;
    int b = bid / (17 * 128);
    int l0 = lblk * 16;
    float w0 = cw[c * 4 + 0], w1 = cw[c * 4 + 1], w2 = cw[c * 4 + 2], w3 = cw[c * 4 + 3];
    float bias = cb[c];
    float x[19];
    #pragma unroll
    for (int i = 0; i < 19; i++) {
        int ls = l0 - 3 + i;
        x[i] = (ls >= 0) ? g_proj[((size_t)(b * Ln + ls)) * PROJW + DINn + c] : 0.f;
    }
    #pragma unroll
    for (int j = 0; j < 16; j++) {
        float acc = fmaf(w0, x[j], fmaf(w1, x[j + 1], fmaf(w2, x[j + 2], fmaf(w3, x[j + 3], bias))));
        g_xbc[((size_t)(b * Ln + l0 + j)) * CONVD + c] = siluf(acc);
    }
}

// ---------------- 5) per-chunk: cumsum, Y_diag + D*xs, local states ----------------
__global__ __launch_bounds__(256) void k_chunk(const float* __restrict__ dskip) {
    extern __shared__ float sm[];
    float* Bsm = sm;
    float* Csm = Bsm + 64 * 129;
    float* Xd  = Csm + 64 * 129;
    float* Ms  = Xd + 64 * 65;
    float* Acs = Ms + 64 * 65;
    float* Dec = Acs + 64;

    int c = blockIdx.x, h = blockIdx.y, b = blockIdx.z;
    int t = threadIdx.x;
    size_t rowbase = ((size_t)(b * Ln + c * Qn)) * CONVD;

    for (int i = t; i < Qn * Nn; i += 256) {
        int s = i >> 7, n = i & 127;
        size_t g = rowbase + (size_t)s * CONVD + DINn;
        Bsm[s * 129 + n] = g_xbc[g + n];
        Csm[s * 129 + n] = g_xbc[g + Nn + n];
    }
    if (t < Qn) Acs[t] = g_a[(size_t)(b * Ln + c * Qn + t) * Hn + h];
    __syncthreads();
    if (t == 0) {
        float r = 0.f;
        for (int i = 0; i < Qn; i++) { r += Acs[i]; Acs[i] = r; }
    }
    __syncthreads();
    if (t < Qn) {
        float aq = Acs[t];
        Dec[t] = expf(Acs[Qn - 1] - aq);
        g_acs[(size_t)(b * Ln + c * Qn + t) * Hn + h] = aq;
        if (t == Qn - 1) g_csum[(size_t)(b * Hn + h) * NCn + c] = aq;
    }
    for (int i = t; i < Qn * Pn; i += 256) {
        int s = i >> 6, p = i & 63;
        float xs = g_xbc[rowbase + (size_t)s * CONVD + h * Pn + p];
        Xd[s * 65 + p] = xs * g_dt[(size_t)(b * Ln + c * Qn + s) * Hn + h];
    }
    __syncthreads();

    {
        int qb = t >> 4, sbq = t & 15;
        int q0 = qb * 4, s0 = sbq * 4;
        float m4[4][4];
        #pragma unroll
        for (int i = 0; i < 4; i++)
            #pragma unroll
            for (int j = 0; j < 4; j++) m4[i][j] = 0.f;
        if (s0 <= q0 + 3) {
            for (int n = 0; n < Nn; n++) {
                float cq[4], bs[4];
                #pragma unroll
                for (int i = 0; i < 4; i++) cq[i] = Csm[(q0 + i) * 129 + n];
                #pragma unroll
                for (int j = 0; j < 4; j++) bs[j] = Bsm[(s0 + j) * 129 + n];
                #pragma unroll
                for (int i = 0; i < 4; i++)
                    #pragma unroll
                    for (int j = 0; j < 4; j++) m4[i][j] = fmaf(cq[i], bs[j], m4[i][j]);
            }
        }
        #pragma unroll
        for (int i = 0; i < 4; i++)
            #pragma unroll
            for (int j = 0; j < 4; j++) {
                int q = q0 + i, s = s0 + j;
                Ms[q * 65 + s] = (s <= q) ? m4[i][j] * expf(Acs[q] - Acs[s]) : 0.f;
            }
    }
    __syncthreads();

    {
        int qb = t >> 4, pb = t & 15;
        int q0 = qb * 4, p0 = pb * 4;
        float y4[4][4];
        #pragma unroll
        for (int i = 0; i < 4; i++)
            #pragma unroll
            for (int j = 0; j < 4; j++) y4[i][j] = 0.f;
        int smax = q0 + 3;
        for (int s = 0; s <= smax; s++) {
            float mv[4], xv[4];
            #pragma unroll
            for (int i = 0; i < 4; i++) mv[i] = Ms[(q0 + i) * 65 + s];
            #pragma unroll
            for (int j = 0; j < 4; j++) xv[j] = Xd[s * 65 + p0 + j];
            #pragma unroll
            for (int i = 0; i < 4; i++)
                #pragma unroll
                for (int j = 0; j < 4; j++) y4[i][j] = fmaf(mv[i], xv[j], y4[i][j]);
        }
        float dsk = dskip[h];
        #pragma unroll
        for (int i = 0; i < 4; i++) {
            int q = q0 + i;
            #pragma unroll
            for (int j = 0; j < 4; j++) {
                int p = p0 + j;
                float xs = g_xbc[rowbase + (size_t)q * CONVD + h * Pn + p];
                g_y[((size_t)(b * Ln + c * Qn + q) * Hn + h) * Pn + p] =
                    y4[i][j] + dsk * xs;
            }
        }
    }

    {
        int pb = t >> 4, nb2 = t & 15;
        int p0 = pb * 4, n0 = nb2 * 8;
        float st[4][8];
        #pragma unroll
        for (int i = 0; i < 4; i++)
            #pragma unroll
            for (int j = 0; j < 8; j++) st[i][j] = 0.f;
        for (int q = 0; q < Qn; q++) {
            float d = Dec[q];
            float xv[4], bv[8];
            #pragma unroll
            for (int i = 0; i < 4; i++) xv[i] = Xd[q * 65 + p0 + i] * d;
            #pragma unroll
            for (int j = 0; j < 8; j++) bv[j] = Bsm[q * 129 + n0 + j];
            #pragma unroll
            for (int i = 0; i < 4; i++)
                #pragma unroll
                for (int j = 0; j < 8; j++) st[i][j] = fmaf(xv[i], bv[j], st[i][j]);
        }
        size_t base = ((size_t)(b * Hn + h) * NCn + c) * (Pn * Nn);
        #pragma unroll
        for (int i = 0; i < 4; i++)
            #pragma unroll
            for (int j = 0; j < 8; j++)
                g_states[base + (size_t)(p0 + i) * Nn + n0 + j] = st[i][j];
    }
}

// ---------------- 6) chunk-level scan, 16-way split over state elements ----------------
__global__ __launch_bounds__(256) void k_scan() {
    int bh = blockIdx.x;
    int e0 = blockIdx.y * 512 + threadIdx.x;
    float S[2];
    S[0] = 0.f; S[1] = 0.f;
    for (int c = 0; c < NCn; c++) {
        size_t base = ((size_t)bh * NCn + c) * (Pn * Nn);
        g_statein[base + e0] = S[0];
        g_statein[base + e0 + 256] = S[1];
        float f = expf(g_csum[(size_t)bh * NCn + c]);
        S[0] = fmaf(f, S[0], g_states[base + e0]);
        S[1] = fmaf(f, S[1], g_states[base + e0 + 256]);
    }
}

// ---------------- 7) Y_off ----------------
__global__ __launch_bounds__(256) void k_yoff() {
    extern __shared__ float sm[];
    float* Ss  = sm;
    float* Csm = Ss + 64 * 129;
    float* Eq  = Csm + 64 * 129;

    int c = blockIdx.x, h = blockIdx.y, b = blockIdx.z;
    int t = threadIdx.x;
    size_t rowbase = ((size_t)(b * Ln + c * Qn)) * CONVD;
    size_t sbase = ((size_t)(b * Hn + h) * NCn + c) * (Pn * Nn);

    for (int i = t; i < Pn * Nn; i += 256) {
        int p = i >> 7, n = i & 127;
        Ss[p * 129 + n] = g_statein[sbase + i];
    }
    for (int i = t; i < Qn * Nn; i += 256) {
        int q = i >> 7, n = i & 127;
        Csm[q * 129 + n] = g_xbc[rowbase + (size_t)q * CONVD + DINn + Nn + n];
    }
    if (t < Qn)
        Eq[t] = expf(g_acs[(size_t)(b * Ln + c * Qn + t) * Hn + h]);
    __syncthreads();

    int qb = t >> 4, pb = t & 15;
    int q0 = qb * 4, p0 = pb * 4;
    float acc[4][4];
    #pragma unroll
    for (int i = 0; i < 4; i++)
        #pragma unroll
        for (int j = 0; j < 4; j++) acc[i][j] = 0.f;
    for (int n = 0; n < Nn; n++) {
        float cq[4], sp[4];
        #pragma unroll
        for (int i = 0; i < 4; i++) cq[i] = Csm[(q0 + i) * 129 + n];
        #pragma unroll
        for (int j = 0; j < 4; j++) sp[j] = Ss[(p0 + j) * 129 + n];
        #pragma unroll
        for (int i = 0; i < 4; i++)
            #pragma unroll
            for (int j = 0; j < 4; j++) acc[i][j] = fmaf(cq[i], sp[j], acc[i][j]);
    }
    #pragma unroll
    for (int i = 0; i < 4; i++) {
        int q = q0 + i;
        float e = Eq[q];
        #pragma unroll
        for (int j = 0; j < 4; j++) {
            int p = p0 + j;
            size_t yi = ((size_t)(b * Ln + c * Qn + q) * Hn + h) * Pn + p;
            g_y[yi] += e * acc[i][j];
        }
    }
}

// ---------------- 8) gated rmsnorm -> fp16 A tiles (K=4096, nch=64) ----------------
__global__ __launch_bounds__(256) void k_gatenorm_split(
    const float* __restrict__ gw, unsigned char* __restrict__ Af) {
    size_t row = blockIdx.x;
    int t = threadIdx.x;
    const float4* py = (const float4*)(g_y + row * DINn);
    const float4* pz = (const float4*)(g_proj + row * PROJW);
    float v[16];
    float ss = 0.f;
    #pragma unroll
    for (int i = 0; i < 4; i++) {
        float4 y4 = py[t * 4 + i];
        float4 z4 = pz[t * 4 + i];
        float x0 = y4.x * siluf(z4.x);
        float x1 = y4.y * siluf(z4.y);
        float x2 = y4.z * siluf(z4.z);
        float x3 = y4.w * siluf(z4.w);
        v[i * 4 + 0] = x0; v[i * 4 + 1] = x1; v[i * 4 + 2] = x2; v[i * 4 + 3] = x3;
        ss += x0 * x0 + x1 * x1 + x2 * x2 + x3 * x3;
    }
    float tot = block_reduce_sum(ss);
    float inv = rsqrtf(tot / (float)DINn + EPSf);
    int mt = (int)(row >> 7), r = (int)(row & 127);
    size_t tb = (size_t)mt * NCH2 * A_CH;
    #pragma unroll
    for (int j = 0; j < 8; j++) {
        int k = t * 16 + j * 2;
        uint32_t u = pack2h(v[j * 2] * inv * gw[k], v[j * 2 + 1] * inv * gw[k + 1]);
        int kc = k >> 6, cc = k & 63;
        size_t off = tb + (size_t)kc * A_CH + swz128((uint32_t)(r * 128 + cc * 2));
        *(uint32_t*)(Af + off) = u;
    }
}

// ---------------- launch ----------------
extern "C" void kernel_launch(void* const* d_in, const int* in_sizes, int n_in,
                              void* d_out, int out_size) {
    const float* hs   = (const float*)d_in[0];
    const float* res  = (const float*)d_in[1];
    const float* nw   = (const float*)d_in[2];
    const float* ipw  = (const float*)d_in[3];
    const float* cw   = (const float*)d_in[4];
    const float* cb   = (const float*)d_in[5];
    const float* alog = (const float*)d_in[6];
    const float* dtb  = (const float*)d_in[7];
    const float* dsk  = (const float*)d_in[8];
    const float* gnw  = (const float*)d_in[9];
    const float* opw  = (const float*)d_in[10];
    float* out = (float*)d_out;

    void *pproj, *pAf, *pBf, *pyfb;
    cudaGetSymbolAddress(&pproj, g_proj);
    cudaGetSymbolAddress(&pAf, g_Af);
    cudaGetSymbolAddress(&pBf, g_Bf);
    cudaGetSymbolAddress(&pyfb, g_y);

    float* resid_ptr = ((size_t)out_size >= 2ull * BLn * Dn)
                           ? out + (size_t)BLn * Dn
                           : (float*)pyfb;

    const int SMEM_CHUNK = (2 * 64 * 129 + 2 * 64 * 65 + 128) * 4;
    const int SMEM_YOFF  = (2 * 64 * 129 + 64) * 4;
    const int SMEM_GEMM  = 1024 + NSTAGE * (16384 + 32768) + 64;
    cudaFuncSetAttribute(k_chunk, cudaFuncAttributeMaxDynamicSharedMemorySize, SMEM_CHUNK);
    cudaFuncSetAttribute(k_yoff,  cudaFuncAttributeMaxDynamicSharedMemorySize, SMEM_YOFF);
    cudaFuncSetAttribute(gemm_mma_fp16, cudaFuncAttributeMaxDynamicSharedMemorySize, SMEM_GEMM);

    // 1) resid + rmsnorm -> fp32 g_h + fp16 A tiles
    k_add_rmsnorm_split<<<BLn, 256>>>(hs, res, nw, resid_ptr, (unsigned char*)pAf);

    // 1b) exact fp32 dt projection + softplus (precision-critical path)
    k_dtproj<<<BLn / 64, 256>>>(ipw, dtb, alog);

    // 2a) transpose in_proj_w -> fp16 B tiles
    {
        dim3 grid(PROJW / 32, Dn / 64);
        k_splitB<<<grid, 256>>>(ipw, (unsigned char*)pBf, PROJW, NCH1);
    }
    // 2b) proj = h @ in_proj_w  (fp16 HMMA, 256-wide tiles, 4-stage)
    {
        dim3 grid(NT1, MTil);
        gemm_mma_fp16<<<grid, 512, SMEM_GEMM>>>(
            (const unsigned char*)pAf, (const unsigned char*)pBf,
            (float*)pproj, PROJW, NCH1);
    }

    // 3) conv + silu (sliding window)
    k_conv2<<<Bn * 128 * 17, 256>>>(cw, cb);

    // 5) chunk kernel
    {
        dim3 grid(NCn, Hn, Bn);
        k_chunk<<<grid, 256, SMEM_CHUNK>>>(dsk);
    }

    // 6) inter-chunk scan (16-way split)
    {
        dim3 grid(Bn * Hn, 16);
        k_scan<<<grid, 256>>>();
    }

    // 7) Y_off
    {
        dim3 grid(NCn, Hn, Bn);
        k_yoff<<<grid, 256, SMEM_YOFF>>>();
    }

    // 8) gated rmsnorm -> fp16 A tiles (K=4096)
    k_gatenorm_split<<<BLn, 256>>>(gnw, (unsigned char*)pAf);

    // 9a) transpose out_proj_w -> fp16 B tiles
    {
        dim3 grid(Dn / 32, DINn / 64);
        k_splitB<<<grid, 256>>>(opw, (unsigned char*)pBf, Dn, NCH2);
    }
    // 9b) out = yg @ out_proj_w  (256-wide tiles, 4-stage)
    {
        dim3 grid(Dn / 256, MTil);
        gemm_mma_fp16<<<grid, 512, SMEM_GEMM>>>(
            (const unsigned char*)pAf, (const unsigned char*)pBf,
            out, Dn, NCH2);
    }
}

// round 12
// speedup vs baseline: 2.0317x; 1.2963x over previous
#include <cuda_runtime.h>
#include <cuda_fp16.h>
#include <math.h>
#include <stdint.h>

// ---------------- problem constants ----------------
#define Bn    2
#define Ln    2048
#define Dn    2048
#define DINn  4096
#define Nn    128
#define Hn    64
#define Pn    64
#define Kc    4
#define CONVD 4352            // DIN + 2*G*N
#define Qn    64
#define NCn   32
#define PROJW 8512            // 2*DIN + 2*G*N + H
#define DTOFF 8448            // DIN + CONVD
#define BLn   (Bn*Ln)         // 4096
#define EPSf  1e-5f

// GEMM tiling: 128(M) x 256(N) block tile, BK=64, 512 threads, fp16 single-pass
#define A_CH  16384
#define B_CH  32768
#define NSTAGE 4

#define NCH1  32
#define NT1   34
#define NCH2  64
#define MTil  32

// ---------------- scratch ----------------
__device__ float g_h[(size_t)BLn*Dn];
__device__ float g_proj[(size_t)BLn*PROJW];
__device__ float g_xbc[(size_t)BLn*CONVD];
__device__ float g_dt[(size_t)BLn*Hn];
__device__ float g_a[(size_t)BLn*Hn];
__device__ float g_acs[(size_t)BLn*Hn];
__device__ float g_csum[(size_t)Bn*Hn*NCn];
__device__ float g_states[(size_t)Bn*Hn*NCn*Pn*Nn];
__device__ float g_statein[(size_t)Bn*Hn*NCn*Pn*Nn];
__device__ float g_y[(size_t)BLn*DINn];

__device__ __align__(1024) unsigned char g_Af[(size_t)MTil*NCH2*A_CH];
__device__ __align__(1024) unsigned char g_Bf[(size_t)NT1*NCH1*B_CH];

// ---------------- PTX helpers ----------------
__device__ __forceinline__ uint32_t smem_u32(const void* p) {
    uint32_t a;
    asm("{ .reg .u64 t; cvta.to.shared.u64 t, %1; cvt.u32.u64 %0, t; }" : "=r"(a) : "l"(p));
    return a;
}
__device__ __forceinline__ uint32_t swz128(uint32_t o) { return o ^ ((o >> 3) & 0x70); }

#define MBAR_INIT(a, c) \
    asm volatile("mbarrier.init.shared.b64 [%0], %1;" :: "r"(a), "r"(c) : "memory")
#define MBAR_EXPECT_TX(a, b) \
    asm volatile("mbarrier.arrive.expect_tx.shared.b64 _, [%0], %1;" :: "r"(a), "r"(b) : "memory")
#define MBAR_WAIT(a, ph) do { \
    uint32_t _m = (a); uint32_t _p = (ph); uint32_t _d; \
    asm volatile("{\n\t.reg .pred p;\n\t" \
        "mbarrier.try_wait.parity.acquire.cta.shared::cta.b64 p, [%1], %2;\n\t" \
        "selp.b32 %0, 1, 0, p;\n\t}" : "=r"(_d) : "r"(_m), "r"(_p) : "memory"); \
    if (!_d) { \
        asm volatile("{\n\t.reg .pred P1;\n\t" \
            "WL_%=:\n\t" \
            "mbarrier.try_wait.parity.acquire.cta.shared::cta.b64 P1, [%0], %1, 0x989680;\n\t" \
            "@P1 bra.uni WD_%=;\n\t" \
            "bra.uni WL_%=;\n\t" \
            "WD_%=:\n\t}" :: "r"(_m), "r"(_p) : "memory"); \
    } \
} while (0)

#define BULK_LD(sa, gp, bytes, mb) \
    asm volatile("cp.async.bulk.shared::cluster.global.mbarrier::complete_tx::bytes [%0], [%1], %2, [%3];" \
        :: "r"(sa), "l"(gp), "r"(bytes), "r"(mb) : "memory")

#define LDSMX4(r, addr) \
    asm volatile("ldmatrix.sync.aligned.m8n8.x4.shared.b16 {%0,%1,%2,%3}, [%4];" \
        : "=r"((r)[0]), "=r"((r)[1]), "=r"((r)[2]), "=r"((r)[3]) : "r"(addr))

#define MMA_FP16(d, a, b0, b1) \
    asm volatile("mma.sync.aligned.m16n8k16.row.col.f32.f16.f16.f32 " \
        "{%0,%1,%2,%3}, {%4,%5,%6,%7}, {%8,%9}, {%0,%1,%2,%3};" \
        : "+f"((d)[0]), "+f"((d)[1]), "+f"((d)[2]), "+f"((d)[3]) \
        : "r"((a)[0]), "r"((a)[1]), "r"((a)[2]), "r"((a)[3]), "r"(b0), "r"(b1))

// ---------------- misc helpers ----------------
__device__ __forceinline__ float block_reduce_sum(float v) {
    __shared__ float red[32];
    int lane = threadIdx.x & 31, wid = threadIdx.x >> 5;
    #pragma unroll
    for (int o = 16; o; o >>= 1) v += __shfl_down_sync(0xffffffffu, v, o);
    if (lane == 0) red[wid] = v;
    __syncthreads();
    v = (threadIdx.x < (blockDim.x >> 5)) ? red[threadIdx.x] : 0.f;
    if (wid == 0) {
        #pragma unroll
        for (int o = 16; o; o >>= 1) v += __shfl_down_sync(0xffffffffu, v, o);
        if (lane == 0) red[0] = v;
    }
    __syncthreads();
    return red[0];
}
__device__ __forceinline__ float siluf(float x) { return x / (1.f + expf(-x)); }

__device__ __forceinline__ uint32_t pack2h(float x0, float x1) {
    __half h0 = __float2half_rn(x0);
    __half h1 = __float2half_rn(x1);
    return ((uint32_t)__half_as_ushort(h1) << 16) | __half_as_ushort(h0);
}

// ---------------- 1) resid + rmsnorm -> fp32 g_h + fp16 A tiles ----------------
__global__ __launch_bounds__(256) void k_add_rmsnorm_split(
    const float* __restrict__ hs, const float* __restrict__ res,
    const float* __restrict__ w, float* __restrict__ resid_out,
    unsigned char* __restrict__ Af) {
    size_t row = blockIdx.x;
    int t = threadIdx.x;
    const float4* ph = (const float4*)(hs + row * Dn);
    const float4* pr = (const float4*)(res + row * Dn);
    float4* po = (float4*)(resid_out + row * Dn);
    float v[8];
    float ss = 0.f;
    #pragma unroll
    for (int i = 0; i < 2; i++) {
        float4 a = ph[t * 2 + i], b = pr[t * 2 + i];
        float4 x = make_float4(a.x + b.x, a.y + b.y, a.z + b.z, a.w + b.w);
        po[t * 2 + i] = x;
        v[i * 4 + 0] = x.x; v[i * 4 + 1] = x.y; v[i * 4 + 2] = x.z; v[i * 4 + 3] = x.w;
        ss += x.x * x.x + x.y * x.y + x.z * x.z + x.w * x.w;
    }
    float tot = block_reduce_sum(ss);
    float inv = rsqrtf(tot / (float)Dn + EPSf);
    int mt = (int)(row >> 7), r = (int)(row & 127);
    size_t tb = (size_t)mt * NCH1 * A_CH;
    float4* gh = (float4*)(g_h + row * Dn);
    #pragma unroll
    for (int i = 0; i < 2; i++) {
        float4 x = make_float4(v[i*4]*inv*w[t*8+i*4], v[i*4+1]*inv*w[t*8+i*4+1],
                               v[i*4+2]*inv*w[t*8+i*4+2], v[i*4+3]*inv*w[t*8+i*4+3]);
        gh[t * 2 + i] = x;
        v[i*4] = x.x; v[i*4+1] = x.y; v[i*4+2] = x.z; v[i*4+3] = x.w;
    }
    #pragma unroll
    for (int j = 0; j < 4; j++) {
        int k = t * 8 + j * 2;
        uint32_t u = pack2h(v[j * 2], v[j * 2 + 1]);
        int kc = k >> 6, c = k & 63;
        size_t off = tb + (size_t)kc * A_CH + swz128((uint32_t)(r * 128 + c * 2));
        *(uint32_t*)(Af + off) = u;
    }
}

// ---------------- weight transpose to fp16 ----------------
__global__ __launch_bounds__(256) void k_splitB(
    const float* __restrict__ W, unsigned char* __restrict__ Bf, int Nreal, int nch) {
    __shared__ float tile[64][33];
    int kb = blockIdx.y * 64;
    int n0 = blockIdx.x * 32;
    int t = threadIdx.x;
    int tx = t & 31, ty = t >> 5;
    #pragma unroll
    for (int i = 0; i < 8; i++) {
        int k = ty + i * 8;
        tile[k][tx] = W[(size_t)(kb + k) * Nreal + n0 + tx];
    }
    __syncthreads();
    int kc = kb >> 6;
    #pragma unroll
    for (int j = 0; j < 4; j++) {
        int nl = ty * 4 + j;
        int n = n0 + nl;
        uint32_t u = pack2h(tile[tx * 2][nl], tile[tx * 2 + 1][nl]);
        int nt = n >> 8, r = n & 255;
        size_t base = ((size_t)(nt * nch + kc)) * B_CH;
        size_t off = base + swz128((uint32_t)(r * 128 + tx * 4));
        *(uint32_t*)(Bf + off) = u;
    }
}

// ---------------- fp16 GEMM (R11-proven, 4-stage) ----------------
__global__ __launch_bounds__(512) void gemm_mma_fp16(
    const unsigned char* __restrict__ Af, const unsigned char* __restrict__ Bf,
    float* __restrict__ C, int Nreal, int nch) {
    constexpr int STGB = 16384 + 32768;
    extern __shared__ unsigned char smg[];
    uint32_t sb = (smem_u32(smg) + 1023) & ~1023u;
    uint32_t ctrl = sb + NSTAGE * STGB;
    int t = threadIdx.x, lane = t & 31, wid = t >> 5;
    int bx = blockIdx.x, by = blockIdx.y;

    if (t == 0) {
        MBAR_INIT(ctrl + 0, 1); MBAR_INIT(ctrl + 8, 1);
        MBAR_INIT(ctrl + 16, 1); MBAR_INIT(ctrl + 24, 1);
    }
    __syncthreads();

    const unsigned char* Ap = Af + (size_t)by * nch * A_CH;
    const unsigned char* Bp = Bf + (size_t)bx * nch * B_CH;

    int wm = wid & 1, wn = wid >> 1;
    int rowA = wm * 64 + (lane & 7) + ((lane >> 3) & 1) * 8;
    int colA = ((lane >> 4) & 1) * 16;
    int rowB = wn * 32 + (lane & 7) + ((lane >> 4) & 1) * 8;
    int colB = ((lane >> 3) & 1) * 16;

    float acc[4][4][4];
    #pragma unroll
    for (int i = 0; i < 4; i++)
        #pragma unroll
        for (int j = 0; j < 4; j++)
            #pragma unroll
            for (int q = 0; q < 4; q++) acc[i][j][q] = 0.f;

    if (t == 0) {
        #pragma unroll
        for (int pc = 0; pc < 3; pc++) {
            if (pc < nch) {
                MBAR_EXPECT_TX(ctrl + pc * 8, STGB);
                BULK_LD(sb + pc * STGB + 0,     Ap + (size_t)pc * A_CH, A_CH, ctrl + pc * 8);
                BULK_LD(sb + pc * STGB + 16384, Bp + (size_t)pc * B_CH, B_CH, ctrl + pc * 8);
            }
        }
    }
    int ph[NSTAGE] = {0, 0, 0, 0};
    for (int kc = 0; kc < nch; kc++) {
        int slot = kc % NSTAGE;
        MBAR_WAIT(ctrl + slot * 8, ph[slot]);
        ph[slot] ^= 1;
        uint32_t s = sb + slot * STGB;
        uint32_t sA = s, sB = s + 16384;
        #pragma unroll
        for (int k = 0; k < 4; k++) {
            uint32_t bh[2][4];
            #pragma unroll
            for (int ib = 0; ib < 2; ib++) {
                uint32_t off = swz128((uint32_t)((rowB + ib * 16) * 128 + k * 32 + colB));
                LDSMX4(bh[ib], sB + off);
            }
            #pragma unroll
            for (int im = 0; im < 4; im++) {
                uint32_t ah[4];
                uint32_t off = swz128((uint32_t)((rowA + im * 16) * 128 + k * 32 + colA));
                LDSMX4(ah, sA + off);
                #pragma unroll
                for (int ib = 0; ib < 2; ib++)
                    #pragma unroll
                    for (int hf = 0; hf < 2; hf++)
                        MMA_FP16(acc[im][ib * 2 + hf], ah, bh[ib][2 * hf], bh[ib][2 * hf + 1]);
            }
        }
        __syncthreads();
        if (t == 0 && kc + 3 < nch) {
            int ns = (kc + 3) % NSTAGE;
            uint32_t d = sb + ns * STGB;
            uint32_t mb = ctrl + ns * 8;
            MBAR_EXPECT_TX(mb, STGB);
            BULK_LD(d + 0,     Ap + (size_t)(kc + 3) * A_CH, A_CH, mb);
            BULK_LD(d + 16384, Bp + (size_t)(kc + 3) * B_CH, B_CH, mb);
        }
    }

    int mBase = by * 128 + wm * 64;
    int nBase = bx * 256 + wn * 32;
    #pragma unroll
    for (int im = 0; im < 4; im++) {
        #pragma unroll
        for (int in = 0; in < 4; in++) {
            int r = mBase + im * 16 + (lane >> 2);
            int c = nBase + in * 8 + (lane & 3) * 2;
            if (c < Nreal) {
                float2 v0 = make_float2(acc[im][in][0], acc[im][in][1]);
                float2 v1 = make_float2(acc[im][in][2], acc[im][in][3]);
                *(float2*)(C + (size_t)r * Nreal + c) = v0;
                *(float2*)(C + (size_t)(r + 8) * Nreal + c) = v1;
            }
        }
    }
}

// ---------------- exact fp32 skinny GEMM for dt columns + softplus ----------------
__global__ __launch_bounds__(256) void k_dtproj(
    const float* __restrict__ ipw, const float* __restrict__ dtb,
    const float* __restrict__ alog) {
    __shared__ float sh[64][68];
    __shared__ float sw[64][68];
    int m0 = blockIdx.x * 64;
    int t = threadIdx.x;
    int tm = t >> 4, tn = t & 15;
    float acc[4][4];
    #pragma unroll
    for (int i = 0; i < 4; i++)
        #pragma unroll
        for (int j = 0; j < 4; j++) acc[i][j] = 0.f;

    for (int kb = 0; kb < Dn; kb += 64) {
        #pragma unroll
        for (int i = 0; i < 16; i++) {
            int idx = t + i * 256;
            int m = idx >> 6, kk = idx & 63;
            sh[kk][m] = g_h[(size_t)(m0 + m) * Dn + kb + kk];
        }
        #pragma unroll
        for (int i = 0; i < 16; i++) {
            int idx = t + i * 256;
            int kk = idx >> 6, h = idx & 63;
            sw[kk][h] = ipw[(size_t)(kb + kk) * PROJW + DTOFF + h];
        }
        __syncthreads();
        #pragma unroll 8
        for (int kk = 0; kk < 64; kk++) {
            float4 ar = *(const float4*)&sh[kk][tm * 4];
            float4 br = *(const float4*)&sw[kk][tn * 4];
            float a4[4] = {ar.x, ar.y, ar.z, ar.w};
            float b4[4] = {br.x, br.y, br.z, br.w};
            #pragma unroll
            for (int i = 0; i < 4; i++)
                #pragma unroll
                for (int j = 0; j < 4; j++) acc[i][j] = fmaf(a4[i], b4[j], acc[i][j]);
        }
        __syncthreads();
    }
    #pragma unroll
    for (int i = 0; i < 4; i++) {
        int m = m0 + tm * 4 + i;
        #pragma unroll
        for (int j = 0; j < 4; j++) {
            int h = tn * 4 + j;
            float x = acc[i][j] + dtb[h];
            float sp = (x > 20.f) ? x : log1pf(expf(x));
            g_dt[(size_t)m * Hn + h] = sp;
            g_a[(size_t)m * Hn + h] = -expf(alog[h]) * sp;
        }
    }
}

// ---------------- 3) causal depthwise conv ----------------
__global__ __launch_bounds__(256) void k_conv2(
    const float* __restrict__ cw, const float* __restrict__ cb) {
    int bid = blockIdx.x;
    int c = (bid % 17) * 256 + threadIdx.x;
    int lblk = (bid / 17) & 127;
    int b = bid / (17 * 128);
    int l0 = lblk * 16;
    float w0 = cw[c * 4 + 0], w1 = cw[c * 4 + 1], w2 = cw[c * 4 + 2], w3 = cw[c * 4 + 3];
    float bias = cb[c];
    float x[19];
    #pragma unroll
    for (int i = 0; i < 19; i++) {
        int ls = l0 - 3 + i;
        x[i] = (ls >= 0) ? g_proj[((size_t)(b * Ln + ls)) * PROJW + DINn + c] : 0.f;
    }
    #pragma unroll
    for (int j = 0; j < 16; j++) {
        float acc = fmaf(w0, x[j], fmaf(w1, x[j + 1], fmaf(w2, x[j + 2], fmaf(w3, x[j + 3], bias))));
        g_xbc[((size_t)(b * Ln + l0 + j)) * CONVD + c] = siluf(acc);
    }
}

// ---------------- 5) per-chunk SSD via HMMA ----------------
// smem layout (bytes): B 0..16K | C 16K..32K | BT 32K..48K | XdT 48K..56K |
//                      XdDT 56K..64K | Ms 64K..72K | Acs 72K.. | Dec ..
#define KC_B   0
#define KC_C   16384
#define KC_BT  32768
#define KC_XT  49152
#define KC_XDT 57344
#define KC_M   65536
#define KC_ACS 73728
#define KC_DEC 73984
#define KC_SMEM 74496

__global__ __launch_bounds__(256) void k_chunk(const float* __restrict__ dskip) {
    extern __shared__ unsigned char smc[];
    uint32_t sb = smem_u32(smc);
    float* Acs = (float*)(smc + KC_ACS);
    float* Dec = (float*)(smc + KC_DEC);

    int c = blockIdx.x, h = blockIdx.y, b = blockIdx.z;
    int t = threadIdx.x, lane = t & 31, wid = t >> 5;
    size_t rowbase = ((size_t)(b * Ln + c * Qn)) * CONVD;

    // fill B/C tiles (fp16, 2 chunks of 64 cols, swizzled)
    for (int i = t; i < 64 * 64; i += 256) {
        int s = i >> 6, cp = i & 63;          // column pair: cols 2cp, 2cp+1
        size_t g = rowbase + (size_t)s * CONVD + DINn + cp * 2;
        float b0 = g_xbc[g], b1 = g_xbc[g + 1];
        float c0 = g_xbc[g + Nn], c1 = g_xbc[g + Nn + 1];
        int chunk = cp >> 5;
        uint32_t off = chunk * 8192 + swz128((uint32_t)(s * 128 + (cp & 31) * 4));
        *(uint32_t*)(smc + KC_B + off) = pack2h(b0, b1);
        *(uint32_t*)(smc + KC_C + off) = pack2h(c0, c1);
    }
    // fill BT tile: [n(128 rows)][q(64 cols)] fp16 swizzled
    for (int i = t; i < 128 * 64; i += 256) {
        int n = i & 127, q = i >> 7;
        float bv = g_xbc[rowbase + (size_t)q * CONVD + DINn + n];
        *(__half*)(smc + KC_BT + swz128((uint32_t)(n * 128 + q * 2))) = __float2half_rn(bv);
    }
    if (t < Qn) Acs[t] = g_a[(size_t)(b * Ln + c * Qn + t) * Hn + h];
    __syncthreads();
    if (t == 0) {
        float r = 0.f;
        for (int i = 0; i < Qn; i++) { r += Acs[i]; Acs[i] = r; }
    }
    __syncthreads();
    if (t < Qn) {
        float aq = Acs[t];
        Dec[t] = expf(Acs[Qn - 1] - aq);
        g_acs[(size_t)(b * Ln + c * Qn + t) * Hn + h] = aq;
        if (t == Qn - 1) g_csum[(size_t)(b * Hn + h) * NCn + c] = aq;
    }
    __syncthreads();
    // fill XdT [p][s] and XdDT [p][q]*Dec
    for (int i = t; i < 64 * 32; i += 256) {
        int p = i & 63, sp = (i >> 6) * 2;
        float x0 = g_xbc[rowbase + (size_t)sp * CONVD + h * Pn + p]
                 * g_dt[(size_t)(b * Ln + c * Qn + sp) * Hn + h];
        float x1 = g_xbc[rowbase + (size_t)(sp + 1) * CONVD + h * Pn + p]
                 * g_dt[(size_t)(b * Ln + c * Qn + sp + 1) * Hn + h];
        uint32_t off = swz128((uint32_t)(p * 128 + sp * 2));
        *(uint32_t*)(smc + KC_XT + off) = pack2h(x0, x1);
        *(uint32_t*)(smc + KC_XDT + off) = pack2h(x0 * Dec[sp], x1 * Dec[sp + 1]);
    }
    __syncthreads();

    // warp layout: wq = wid&3 (16-row group), ws = wid>>2 (0/1)
    int wq = wid & 3, ws = wid >> 2;
    int rA = wq * 16 + (lane & 7) + ((lane >> 3) & 1) * 8;
    int cA = ((lane >> 4) & 1) * 16;
    int rB = ws * 32 + (lane & 7) + ((lane >> 4) & 1) * 8;
    int cB = ((lane >> 3) & 1) * 16;

    // --- M = C @ B^T (64x64x128) ---
    float mAcc[4][4];
    #pragma unroll
    for (int i = 0; i < 4; i++)
        #pragma unroll
        for (int j = 0; j < 4; j++) mAcc[i][j] = 0.f;
    #pragma unroll
    for (int ch = 0; ch < 2; ch++) {
        #pragma unroll
        for (int k = 0; k < 4; k++) {
            uint32_t ah[4];
            LDSMX4(ah, sb + KC_C + ch * 8192 + swz128((uint32_t)(rA * 128 + k * 32 + cA)));
            uint32_t bh[2][4];
            #pragma unroll
            for (int ib = 0; ib < 2; ib++)
                LDSMX4(bh[ib], sb + KC_B + ch * 8192 +
                       swz128((uint32_t)((rB + ib * 16) * 128 + k * 32 + cB)));
            #pragma unroll
            for (int ib = 0; ib < 2; ib++)
                #pragma unroll
                for (int hf = 0; hf < 2; hf++)
                    MMA_FP16(mAcc[ib * 2 + hf], ah, bh[ib][2 * hf], bh[ib][2 * hf + 1]);
        }
    }
    // write Ms = mask(s<=q) * M * exp(Acs[q]-Acs[s]), fp16 swizzled
    {
        int q0 = wq * 16 + (lane >> 2);
        int sc0 = ws * 32 + (lane & 3) * 2;
        #pragma unroll
        for (int nt = 0; nt < 4; nt++) {
            int sc = sc0 + nt * 8;
            #pragma unroll
            for (int r2 = 0; r2 < 2; r2++) {
                int q = q0 + r2 * 8;
                float aq = Acs[q];
                float v0 = (sc <= q)     ? mAcc[nt][r2 * 2 + 0] * expf(aq - Acs[sc])     : 0.f;
                float v1 = (sc + 1 <= q) ? mAcc[nt][r2 * 2 + 1] * expf(aq - Acs[sc + 1]) : 0.f;
                *(uint32_t*)(smc + KC_M + swz128((uint32_t)(q * 128 + sc * 2))) = pack2h(v0, v1);
            }
        }
    }
    __syncthreads();

    // --- Y_diag = Ms @ XdT^T (64x64x64) + D_skip*xs -> g_y ---
    {
        float yAcc[4][4];
        #pragma unroll
        for (int i = 0; i < 4; i++)
            #pragma unroll
            for (int j = 0; j < 4; j++) yAcc[i][j] = 0.f;
        #pragma unroll
        for (int k = 0; k < 4; k++) {
            uint32_t ah[4];
            LDSMX4(ah, sb + KC_M + swz128((uint32_t)(rA * 128 + k * 32 + cA)));
            uint32_t bh[2][4];
            #pragma unroll
            for (int ib = 0; ib < 2; ib++)
                LDSMX4(bh[ib], sb + KC_XT +
                       swz128((uint32_t)((rB + ib * 16) * 128 + k * 32 + cB)));
            #pragma unroll
            for (int ib = 0; ib < 2; ib++)
                #pragma unroll
                for (int hf = 0; hf < 2; hf++)
                    MMA_FP16(yAcc[ib * 2 + hf], ah, bh[ib][2 * hf], bh[ib][2 * hf + 1]);
        }
        float dsk = dskip[h];
        int q0 = wq * 16 + (lane >> 2);
        int p0 = ws * 32 + (lane & 3) * 2;
        #pragma unroll
        for (int nt = 0; nt < 4; nt++) {
            int p = p0 + nt * 8;
            #pragma unroll
            for (int r2 = 0; r2 < 2; r2++) {
                int q = q0 + r2 * 8;
                float2 xs2 = *(const float2*)(g_xbc + rowbase + (size_t)q * CONVD + h * Pn + p);
                float2 o;
                o.x = yAcc[nt][r2 * 2 + 0] + dsk * xs2.x;
                o.y = yAcc[nt][r2 * 2 + 1] + dsk * xs2.y;
                *(float2*)(g_y + ((size_t)(b * Ln + c * Qn + q) * Hn + h) * Pn + p) = o;
            }
        }
    }

    // --- states = XdDT @ BT^T (64x128x64) -> g_states ---
    {
        float sAcc[8][4];
        #pragma unroll
        for (int i = 0; i < 8; i++)
            #pragma unroll
            for (int j = 0; j < 4; j++) sAcc[i][j] = 0.f;
        int rBs = ws * 64 + (lane & 7) + ((lane >> 4) & 1) * 8;
        #pragma unroll
        for (int k = 0; k < 4; k++) {
            uint32_t ah[4];
            LDSMX4(ah, sb + KC_XDT + swz128((uint32_t)(rA * 128 + k * 32 + cA)));
            uint32_t bh[4][4];
            #pragma unroll
            for (int ib = 0; ib < 4; ib++)
                LDSMX4(bh[ib], sb + KC_BT +
                       swz128((uint32_t)((rBs + ib * 16) * 128 + k * 32 + cB)));
            #pragma unroll
            for (int ib = 0; ib < 4; ib++)
                #pragma unroll
                for (int hf = 0; hf < 2; hf++)
                    MMA_FP16(sAcc[ib * 2 + hf], ah, bh[ib][2 * hf], bh[ib][2 * hf + 1]);
        }
        size_t base = ((size_t)(b * Hn + h) * NCn + c) * (Pn * Nn);
        int p0 = wq * 16 + (lane >> 2);
        int n0 = ws * 64 + (lane & 3) * 2;
        #pragma unroll
        for (int nt = 0; nt < 8; nt++) {
            int n = n0 + nt * 8;
            #pragma unroll
            for (int r2 = 0; r2 < 2; r2++) {
                int p = p0 + r2 * 8;
                float2 o = make_float2(sAcc[nt][r2 * 2 + 0], sAcc[nt][r2 * 2 + 1]);
                *(float2*)(g_states + base + (size_t)p * Nn + n) = o;
            }
        }
    }
}

// ---------------- 6) chunk-level scan ----------------
__global__ __launch_bounds__(256) void k_scan() {
    int bh = blockIdx.x;
    int e0 = blockIdx.y * 512 + threadIdx.x;
    float S[2];
    S[0] = 0.f; S[1] = 0.f;
    for (int c = 0; c < NCn; c++) {
        size_t base = ((size_t)bh * NCn + c) * (Pn * Nn);
        g_statein[base + e0] = S[0];
        g_statein[base + e0 + 256] = S[1];
        float f = expf(g_csum[(size_t)bh * NCn + c]);
        S[0] = fmaf(f, S[0], g_states[base + e0]);
        S[1] = fmaf(f, S[1], g_states[base + e0 + 256]);
    }
}

// ---------------- 7) Y_off via HMMA: Y[q][p] += Eq[q] * sum_n C[q][n] S[p][n] ----------------
#define KY_C   0
#define KY_S   16384
#define KY_EQ  32768
#define KY_SMEM 33280

__global__ __launch_bounds__(256) void k_yoff() {
    extern __shared__ unsigned char smy[];
    uint32_t sb = smem_u32(smy);
    float* Eq = (float*)(smy + KY_EQ);

    int c = blockIdx.x, h = blockIdx.y, b = blockIdx.z;
    int t = threadIdx.x, lane = t & 31, wid = t >> 5;
    size_t rowbase = ((size_t)(b * Ln + c * Qn)) * CONVD;
    size_t sbase = ((size_t)(b * Hn + h) * NCn + c) * (Pn * Nn);

    // fill C tile (fp16, 2 chunks)
    for (int i = t; i < 64 * 64; i += 256) {
        int q = i >> 6, cp = i & 63;
        size_t g = rowbase + (size_t)q * CONVD + DINn + Nn + cp * 2;
        int chunk = cp >> 5;
        uint32_t off = chunk * 8192 + swz128((uint32_t)(q * 128 + (cp & 31) * 4));
        *(uint32_t*)(smy + KY_C + off) = pack2h(g_xbc[g], g_xbc[g + 1]);
    }
    // fill S tile [p][n] fp16 (2 chunks along n)
    for (int i = t; i < 64 * 64; i += 256) {
        int p = i >> 6, np = i & 63;
        const float* sp = g_statein + sbase + (size_t)p * Nn + np * 2;
        int chunk = np >> 5;
        uint32_t off = chunk * 8192 + swz128((uint32_t)(p * 128 + (np & 31) * 4));
        *(uint32_t*)(smy + KY_S + off) = pack2h(sp[0], sp[1]);
    }
    if (t < Qn)
        Eq[t] = expf(g_acs[(size_t)(b * Ln + c * Qn + t) * Hn + h]);
    __syncthreads();

    int wq = wid & 3, ws = wid >> 2;
    int rA = wq * 16 + (lane & 7) + ((lane >> 3) & 1) * 8;
    int cA = ((lane >> 4) & 1) * 16;
    int rB = ws * 32 + (lane & 7) + ((lane >> 4) & 1) * 8;
    int cB = ((lane >> 3) & 1) * 16;

    float acc[4][4];
    #pragma unroll
    for (int i = 0; i < 4; i++)
        #pragma unroll
        for (int j = 0; j < 4; j++) acc[i][j] = 0.f;
    #pragma unroll
    for (int ch = 0; ch < 2; ch++) {
        #pragma unroll
        for (int k = 0; k < 4; k++) {
            uint32_t ah[4];
            LDSMX4(ah, sb + KY_C + ch * 8192 + swz128((uint32_t)(rA * 128 + k * 32 + cA)));
            uint32_t bh[2][4];
            #pragma unroll
            for (int ib = 0; ib < 2; ib++)
                LDSMX4(bh[ib], sb + KY_S + ch * 8192 +
                       swz128((uint32_t)((rB + ib * 16) * 128 + k * 32 + cB)));
            #pragma unroll
            for (int ib = 0; ib < 2; ib++)
                #pragma unroll
                for (int hf = 0; hf < 2; hf++)
                    MMA_FP16(acc[ib * 2 + hf], ah, bh[ib][2 * hf], bh[ib][2 * hf + 1]);
        }
    }
    int q0 = wq * 16 + (lane >> 2);
    int p0 = ws * 32 + (lane & 3) * 2;
    #pragma unroll
    for (int nt = 0; nt < 4; nt++) {
        int p = p0 + nt * 8;
        #pragma unroll
        for (int r2 = 0; r2 < 2; r2++) {
            int q = q0 + r2 * 8;
            float e = Eq[q];
            float* dst = g_y + ((size_t)(b * Ln + c * Qn + q) * Hn + h) * Pn + p;
            float2 cur = *(float2*)dst;
            cur.x += e * acc[nt][r2 * 2 + 0];
            cur.y += e * acc[nt][r2 * 2 + 1];
            *(float2*)dst = cur;
        }
    }
}

// ---------------- 8) gated rmsnorm -> fp16 A tiles ----------------
__global__ __launch_bounds__(256) void k_gatenorm_split(
    const float* __restrict__ gw, unsigned char* __restrict__ Af) {
    size_t row = blockIdx.x;
    int t = threadIdx.x;
    const float4* py = (const float4*)(g_y + row * DINn);
    const float4* pz = (const float4*)(g_proj + row * PROJW);
    float v[16];
    float ss = 0.f;
    #pragma unroll
    for (int i = 0; i < 4; i++) {
        float4 y4 = py[t * 4 + i];
        float4 z4 = pz[t * 4 + i];
        float x0 = y4.x * siluf(z4.x);
        float x1 = y4.y * siluf(z4.y);
        float x2 = y4.z * siluf(z4.z);
        float x3 = y4.w * siluf(z4.w);
        v[i * 4 + 0] = x0; v[i * 4 + 1] = x1; v[i * 4 + 2] = x2; v[i * 4 + 3] = x3;
        ss += x0 * x0 + x1 * x1 + x2 * x2 + x3 * x3;
    }
    float tot = block_reduce_sum(ss);
    float inv = rsqrtf(tot / (float)DINn + EPSf);
    int mt = (int)(row >> 7), r = (int)(row & 127);
    size_t tb = (size_t)mt * NCH2 * A_CH;
    #pragma unroll
    for (int j = 0; j < 8; j++) {
        int k = t * 16 + j * 2;
        uint32_t u = pack2h(v[j * 2] * inv * gw[k], v[j * 2 + 1] * inv * gw[k + 1]);
        int kc = k >> 6, cc = k & 63;
        size_t off = tb + (size_t)kc * A_CH + swz128((uint32_t)(r * 128 + cc * 2));
        *(uint32_t*)(Af + off) = u;
    }
}

// ---------------- launch ----------------
extern "C" void kernel_launch(void* const* d_in, const int* in_sizes, int n_in,
                              void* d_out, int out_size) {
    const float* hs   = (const float*)d_in[0];
    const float* res  = (const float*)d_in[1];
    const float* nw   = (const float*)d_in[2];
    const float* ipw  = (const float*)d_in[3];
    const float* cw   = (const float*)d_in[4];
    const float* cb   = (const float*)d_in[5];
    const float* alog = (const float*)d_in[6];
    const float* dtb  = (const float*)d_in[7];
    const float* dsk  = (const float*)d_in[8];
    const float* gnw  = (const float*)d_in[9];
    const float* opw  = (const float*)d_in[10];
    float* out = (float*)d_out;

    void *pproj, *pAf, *pBf, *pyfb;
    cudaGetSymbolAddress(&pproj, g_proj);
    cudaGetSymbolAddress(&pAf, g_Af);
    cudaGetSymbolAddress(&pBf, g_Bf);
    cudaGetSymbolAddress(&pyfb, g_y);

    float* resid_ptr = ((size_t)out_size >= 2ull * BLn * Dn)
                           ? out + (size_t)BLn * Dn
                           : (float*)pyfb;

    const int SMEM_GEMM = 1024 + NSTAGE * (16384 + 32768) + 64;
    cudaFuncSetAttribute(k_chunk, cudaFuncAttributeMaxDynamicSharedMemorySize, KC_SMEM);
    cudaFuncSetAttribute(k_yoff,  cudaFuncAttributeMaxDynamicSharedMemorySize, KY_SMEM);
    cudaFuncSetAttribute(gemm_mma_fp16, cudaFuncAttributeMaxDynamicSharedMemorySize, SMEM_GEMM);

    k_add_rmsnorm_split<<<BLn, 256>>>(hs, res, nw, resid_ptr, (unsigned char*)pAf);
    k_dtproj<<<BLn / 64, 256>>>(ipw, dtb, alog);

    {
        dim3 grid(PROJW / 32, Dn / 64);
        k_splitB<<<grid, 256>>>(ipw, (unsigned char*)pBf, PROJW, NCH1);
    }
    {
        dim3 grid(NT1, MTil);
        gemm_mma_fp16<<<grid, 512, SMEM_GEMM>>>(
            (const unsigned char*)pAf, (const unsigned char*)pBf,
            (float*)pproj, PROJW, NCH1);
    }

    k_conv2<<<Bn * 128 * 17, 256>>>(cw, cb);

    {
        dim3 grid(NCn, Hn, Bn);
        k_chunk<<<grid, 256, KC_SMEM>>>(dsk);
    }
    {
        dim3 grid(Bn * Hn, 16);
        k_scan<<<grid, 256>>>();
    }
    {
        dim3 grid(NCn, Hn, Bn);
        k_yoff<<<grid, 256, KY_SMEM>>>();
    }

    k_gatenorm_split<<<BLn, 256>>>(gnw, (unsigned char*)pAf);

    {
        dim3 grid(Dn / 32, DINn / 64);
        k_splitB<<<grid, 256>>>(opw, (unsigned char*)pBf, Dn, NCH2);
    }
    {
        dim3 grid(Dn / 256, MTil);
        gemm_mma_fp16<<<grid, 512, SMEM_GEMM>>>(
            (const unsigned char*)pAf, (const unsigned char*)pBf,
            out, Dn, NCH2);
    }
}

// round 13
// speedup vs baseline: 2.1282x; 1.0475x over previous
#include <cuda_runtime.h>
#include <cuda_fp16.h>
#include <math.h>
#include <stdint.h>

// ---------------- problem constants ----------------
#define Bn    2
#define Ln    2048
#define Dn    2048
#define DINn  4096
#define Nn    128
#define Hn    64
#define Pn    64
#define Kc    4
#define CONVD 4352            // DIN + 2*G*N
#define Qn    64
#define NCn   32
#define PROJW 8512            // 2*DIN + 2*G*N + H
#define DTOFF 8448            // DIN + CONVD
#define BLn   (Bn*Ln)         // 4096
#define EPSf  1e-5f

// GEMM tiling: 128(M) x 256(N) block tile, BK=64, 512 threads, fp16 single-pass
#define A_CH  16384
#define B_CH  32768
#define NSTAGE 4

#define NCH1  32
#define NT1   33              // 33*256 = 8448: z + xBC only (dt block handled by k_dtproj)
#define NTB1  34              // B-tile buffer extent (k_splitB still writes all 8512 cols)
#define NCH2  64
#define MTil  32

// ---------------- scratch ----------------
__device__ float g_h[(size_t)BLn*Dn];
__device__ float g_proj[(size_t)BLn*PROJW];
__device__ float g_xbc[(size_t)BLn*CONVD];
__device__ float g_dt[(size_t)BLn*Hn];
__device__ float g_a[(size_t)BLn*Hn];
__device__ float g_acs[(size_t)BLn*Hn];
__device__ float g_csum[(size_t)Bn*Hn*NCn];
__device__ float g_states[(size_t)Bn*Hn*NCn*Pn*Nn];
__device__ float g_statein[(size_t)Bn*Hn*NCn*Pn*Nn];
__device__ float g_y[(size_t)BLn*DINn];

__device__ __align__(1024) unsigned char g_Af[(size_t)MTil*NCH2*A_CH];
__device__ __align__(1024) unsigned char g_Bf[(size_t)NTB1*NCH1*B_CH];

// ---------------- PTX helpers ----------------
__device__ __forceinline__ uint32_t smem_u32(const void* p) {
    uint32_t a;
    asm("{ .reg .u64 t; cvta.to.shared.u64 t, %1; cvt.u32.u64 %0, t; }" : "=r"(a) : "l"(p));
    return a;
}
__device__ __forceinline__ uint32_t swz128(uint32_t o) { return o ^ ((o >> 3) & 0x70); }

#define MBAR_INIT(a, c) \
    asm volatile("mbarrier.init.shared.b64 [%0], %1;" :: "r"(a), "r"(c) : "memory")
#define MBAR_EXPECT_TX(a, b) \
    asm volatile("mbarrier.arrive.expect_tx.shared.b64 _, [%0], %1;" :: "r"(a), "r"(b) : "memory")
#define MBAR_WAIT(a, ph) do { \
    uint32_t _m = (a); uint32_t _p = (ph); uint32_t _d; \
    asm volatile("{\n\t.reg .pred p;\n\t" \
        "mbarrier.try_wait.parity.acquire.cta.shared::cta.b64 p, [%1], %2;\n\t" \
        "selp.b32 %0, 1, 0, p;\n\t}" : "=r"(_d) : "r"(_m), "r"(_p) : "memory"); \
    if (!_d) { \
        asm volatile("{\n\t.reg .pred P1;\n\t" \
            "WL_%=:\n\t" \
            "mbarrier.try_wait.parity.acquire.cta.shared::cta.b64 P1, [%0], %1, 0x989680;\n\t" \
            "@P1 bra.uni WD_%=;\n\t" \
            "bra.uni WL_%=;\n\t" \
            "WD_%=:\n\t}" :: "r"(_m), "r"(_p) : "memory"); \
    } \
} while (0)

#define BULK_LD(sa, gp, bytes, mb) \
    asm volatile("cp.async.bulk.shared::cluster.global.mbarrier::complete_tx::bytes [%0], [%1], %2, [%3];" \
        :: "r"(sa), "l"(gp), "r"(bytes), "r"(mb) : "memory")

#define LDSMX4(r, addr) \
    asm volatile("ldmatrix.sync.aligned.m8n8.x4.shared.b16 {%0,%1,%2,%3}, [%4];" \
        : "=r"((r)[0]), "=r"((r)[1]), "=r"((r)[2]), "=r"((r)[3]) : "r"(addr))

#define MMA_FP16(d, a, b0, b1) \
    asm volatile("mma.sync.aligned.m16n8k16.row.col.f32.f16.f16.f32 " \
        "{%0,%1,%2,%3}, {%4,%5,%6,%7}, {%8,%9}, {%0,%1,%2,%3};" \
        : "+f"((d)[0]), "+f"((d)[1]), "+f"((d)[2]), "+f"((d)[3]) \
        : "r"((a)[0]), "r"((a)[1]), "r"((a)[2]), "r"((a)[3]), "r"(b0), "r"(b1))

// ---------------- misc helpers ----------------
__device__ __forceinline__ float block_reduce_sum(float v) {
    __shared__ float red[32];
    int lane = threadIdx.x & 31, wid = threadIdx.x >> 5;
    #pragma unroll
    for (int o = 16; o; o >>= 1) v += __shfl_down_sync(0xffffffffu, v, o);
    if (lane == 0) red[wid] = v;
    __syncthreads();
    v = (threadIdx.x < (blockDim.x >> 5)) ? red[threadIdx.x] : 0.f;
    if (wid == 0) {
        #pragma unroll
        for (int o = 16; o; o >>= 1) v += __shfl_down_sync(0xffffffffu, v, o);
        if (lane == 0) red[0] = v;
    }
    __syncthreads();
    return red[0];
}
__device__ __forceinline__ float siluf(float x) { return x / (1.f + expf(-x)); }

__device__ __forceinline__ uint32_t pack2h(float x0, float x1) {
    __half h0 = __float2half_rn(x0);
    __half h1 = __float2half_rn(x1);
    return ((uint32_t)__half_as_ushort(h1) << 16) | __half_as_ushort(h0);
}

// ---------------- 1) resid + rmsnorm -> fp32 g_h + fp16 A tiles ----------------
__global__ __launch_bounds__(256) void k_add_rmsnorm_split(
    const float* __restrict__ hs, const float* __restrict__ res,
    const float* __restrict__ w, float* __restrict__ resid_out,
    unsigned char* __restrict__ Af) {
    size_t row = blockIdx.x;
    int t = threadIdx.x;
    const float4* ph = (const float4*)(hs + row * Dn);
    const float4* pr = (const float4*)(res + row * Dn);
    float4* po = (float4*)(resid_out + row * Dn);
    float v[8];
    float ss = 0.f;
    #pragma unroll
    for (int i = 0; i < 2; i++) {
        float4 a = ph[t * 2 + i], b = pr[t * 2 + i];
        float4 x = make_float4(a.x + b.x, a.y + b.y, a.z + b.z, a.w + b.w);
        po[t * 2 + i] = x;
        v[i * 4 + 0] = x.x; v[i * 4 + 1] = x.y; v[i * 4 + 2] = x.z; v[i * 4 + 3] = x.w;
        ss += x.x * x.x + x.y * x.y + x.z * x.z + x.w * x.w;
    }
    float tot = block_reduce_sum(ss);
    float inv = rsqrtf(tot / (float)Dn + EPSf);
    int mt = (int)(row >> 7), r = (int)(row & 127);
    size_t tb = (size_t)mt * NCH1 * A_CH;
    float4* gh = (float4*)(g_h + row * Dn);
    #pragma unroll
    for (int i = 0; i < 2; i++) {
        float4 x = make_float4(v[i*4]*inv*w[t*8+i*4], v[i*4+1]*inv*w[t*8+i*4+1],
                               v[i*4+2]*inv*w[t*8+i*4+2], v[i*4+3]*inv*w[t*8+i*4+3]);
        gh[t * 2 + i] = x;
        v[i*4] = x.x; v[i*4+1] = x.y; v[i*4+2] = x.z; v[i*4+3] = x.w;
    }
    #pragma unroll
    for (int j = 0; j < 4; j++) {
        int k = t * 8 + j * 2;
        uint32_t u = pack2h(v[j * 2], v[j * 2 + 1]);
        int kc = k >> 6, c = k & 63;
        size_t off = tb + (size_t)kc * A_CH + swz128((uint32_t)(r * 128 + c * 2));
        *(uint32_t*)(Af + off) = u;
    }
}

// ---------------- weight transpose to fp16 ----------------
__global__ __launch_bounds__(256) void k_splitB(
    const float* __restrict__ W, unsigned char* __restrict__ Bf, int Nreal, int nch) {
    __shared__ float tile[64][33];
    int kb = blockIdx.y * 64;
    int n0 = blockIdx.x * 32;
    int t = threadIdx.x;
    int tx = t & 31, ty = t >> 5;
    #pragma unroll
    for (int i = 0; i < 8; i++) {
        int k = ty + i * 8;
        tile[k][tx] = W[(size_t)(kb + k) * Nreal + n0 + tx];
    }
    __syncthreads();
    int kc = kb >> 6;
    #pragma unroll
    for (int j = 0; j < 4; j++) {
        int nl = ty * 4 + j;
        int n = n0 + nl;
        uint32_t u = pack2h(tile[tx * 2][nl], tile[tx * 2 + 1][nl]);
        int nt = n >> 8, r = n & 255;
        size_t base = ((size_t)(nt * nch + kc)) * B_CH;
        size_t off = base + swz128((uint32_t)(r * 128 + tx * 4));
        *(uint32_t*)(Bf + off) = u;
    }
}

// ---------------- fp16 GEMM: 4-stage, paired-chunk consumption ----------------
__global__ __launch_bounds__(512) void gemm_mma_fp16(
    const unsigned char* __restrict__ Af, const unsigned char* __restrict__ Bf,
    float* __restrict__ C, int Nreal, int nch) {
    constexpr int STGB = 16384 + 32768;
    extern __shared__ unsigned char smg[];
    uint32_t sb = (smem_u32(smg) + 1023) & ~1023u;
    uint32_t ctrl = sb + NSTAGE * STGB;
    int t = threadIdx.x, lane = t & 31, wid = t >> 5;
    int bx = blockIdx.x, by = blockIdx.y;

    if (t == 0) {
        MBAR_INIT(ctrl + 0, 1); MBAR_INIT(ctrl + 8, 1);
        MBAR_INIT(ctrl + 16, 1); MBAR_INIT(ctrl + 24, 1);
    }
    __syncthreads();

    const unsigned char* Ap = Af + (size_t)by * nch * A_CH;
    const unsigned char* Bp = Bf + (size_t)bx * nch * B_CH;

    int wm = wid & 1, wn = wid >> 1;
    int rowA = wm * 64 + (lane & 7) + ((lane >> 3) & 1) * 8;
    int colA = ((lane >> 4) & 1) * 16;
    int rowB = wn * 32 + (lane & 7) + ((lane >> 4) & 1) * 8;
    int colB = ((lane >> 3) & 1) * 16;

    float acc[4][4][4];
    #pragma unroll
    for (int i = 0; i < 4; i++)
        #pragma unroll
        for (int j = 0; j < 4; j++)
            #pragma unroll
            for (int q = 0; q < 4; q++) acc[i][j][q] = 0.f;

    // prologue: fill all 4 slots (nch >= 4 always: 32 or 64)
    if (t == 0) {
        #pragma unroll
        for (int pc = 0; pc < 4; pc++) {
            MBAR_EXPECT_TX(ctrl + pc * 8, STGB);
            BULK_LD(sb + pc * STGB + 0,     Ap + (size_t)pc * A_CH, A_CH, ctrl + pc * 8);
            BULK_LD(sb + pc * STGB + 16384, Bp + (size_t)pc * B_CH, B_CH, ctrl + pc * 8);
        }
    }
    int ph[NSTAGE] = {0, 0, 0, 0};
    for (int kc = 0; kc < nch; kc += 2) {
        #pragma unroll
        for (int half = 0; half < 2; half++) {
            int slot = (kc + half) % NSTAGE;
            MBAR_WAIT(ctrl + slot * 8, ph[slot]);
            ph[slot] ^= 1;
            uint32_t s = sb + slot * STGB;
            uint32_t sA = s, sB = s + 16384;
            #pragma unroll
            for (int k = 0; k < 4; k++) {
                uint32_t bh[2][4];
                #pragma unroll
                for (int ib = 0; ib < 2; ib++) {
                    uint32_t off = swz128((uint32_t)((rowB + ib * 16) * 128 + k * 32 + colB));
                    LDSMX4(bh[ib], sB + off);
                }
                #pragma unroll
                for (int im = 0; im < 4; im++) {
                    uint32_t ah[4];
                    uint32_t off = swz128((uint32_t)((rowA + im * 16) * 128 + k * 32 + colA));
                    LDSMX4(ah, sA + off);
                    #pragma unroll
                    for (int ib = 0; ib < 2; ib++)
                        #pragma unroll
                        for (int hf = 0; hf < 2; hf++)
                            MMA_FP16(acc[im][ib * 2 + hf], ah, bh[ib][2 * hf], bh[ib][2 * hf + 1]);
                }
            }
        }
        __syncthreads();
        // refill the two just-consumed slots with chunks kc+4, kc+5
        if (t == 0) {
            #pragma unroll
            for (int half = 0; half < 2; half++) {
                int nc = kc + 4 + half;
                if (nc < nch) {
                    int ns = nc % NSTAGE;   // == (kc+half)%NSTAGE, just consumed + synced
                    uint32_t d = sb + ns * STGB;
                    uint32_t mb = ctrl + ns * 8;
                    MBAR_EXPECT_TX(mb, STGB);
                    BULK_LD(d + 0,     Ap + (size_t)nc * A_CH, A_CH, mb);
                    BULK_LD(d + 16384, Bp + (size_t)nc * B_CH, B_CH, mb);
                }
            }
        }
    }

    int mBase = by * 128 + wm * 64;
    int nBase = bx * 256 + wn * 32;
    #pragma unroll
    for (int im = 0; im < 4; im++) {
        #pragma unroll
        for (int in = 0; in < 4; in++) {
            int r = mBase + im * 16 + (lane >> 2);
            int c = nBase + in * 8 + (lane & 3) * 2;
            if (c < Nreal) {
                float2 v0 = make_float2(acc[im][in][0], acc[im][in][1]);
                float2 v1 = make_float2(acc[im][in][2], acc[im][in][3]);
                *(float2*)(C + (size_t)r * Nreal + c) = v0;
                *(float2*)(C + (size_t)(r + 8) * Nreal + c) = v1;
            }
        }
    }
}

// ---------------- exact fp32 skinny GEMM for dt columns + softplus ----------------
__global__ __launch_bounds__(256) void k_dtproj(
    const float* __restrict__ ipw, const float* __restrict__ dtb,
    const float* __restrict__ alog) {
    __shared__ float sh[64][68];
    __shared__ float sw[64][68];
    int m0 = blockIdx.x * 64;
    int t = threadIdx.x;
    int tm = t >> 4, tn = t & 15;
    float acc[4][4];
    #pragma unroll
    for (int i = 0; i < 4; i++)
        #pragma unroll
        for (int j = 0; j < 4; j++) acc[i][j] = 0.f;

    for (int kb = 0; kb < Dn; kb += 64) {
        #pragma unroll
        for (int i = 0; i < 16; i++) {
            int idx = t + i * 256;
            int m = idx >> 6, kk = idx & 63;
            sh[kk][m] = g_h[(size_t)(m0 + m) * Dn + kb + kk];
        }
        #pragma unroll
        for (int i = 0; i < 16; i++) {
            int idx = t + i * 256;
            int kk = idx >> 6, h = idx & 63;
            sw[kk][h] = ipw[(size_t)(kb + kk) * PROJW + DTOFF + h];
        }
        __syncthreads();
        #pragma unroll 8
        for (int kk = 0; kk < 64; kk++) {
            float4 ar = *(const float4*)&sh[kk][tm * 4];
            float4 br = *(const float4*)&sw[kk][tn * 4];
            float a4[4] = {ar.x, ar.y, ar.z, ar.w};
            float b4[4] = {br.x, br.y, br.z, br.w};
            #pragma unroll
            for (int i = 0; i < 4; i++)
                #pragma unroll
                for (int j = 0; j < 4; j++) acc[i][j] = fmaf(a4[i], b4[j], acc[i][j]);
        }
        __syncthreads();
    }
    #pragma unroll
    for (int i = 0; i < 4; i++) {
        int m = m0 + tm * 4 + i;
        #pragma unroll
        for (int j = 0; j < 4; j++) {
            int h = tn * 4 + j;
            float x = acc[i][j] + dtb[h];
            float sp = (x > 20.f) ? x : log1pf(expf(x));
            g_dt[(size_t)m * Hn + h] = sp;
            g_a[(size_t)m * Hn + h] = -expf(alog[h]) * sp;
        }
    }
}

// ---------------- 3) causal depthwise conv ----------------
__global__ __launch_bounds__(256) void k_conv2(
    const float* __restrict__ cw, const float* __restrict__ cb) {
    int bid = blockIdx.x;
    int c = (bid % 17) * 256 + threadIdx.x;
    int lblk = (bid / 17) & 127;
    int b = bid / (17 * 128);
    int l0 = lblk * 16;
    float w0 = cw[c * 4 + 0], w1 = cw[c * 4 + 1], w2 = cw[c * 4 + 2], w3 = cw[c * 4 + 3];
    float bias = cb[c];
    float x[19];
    #pragma unroll
    for (int i = 0; i < 19; i++) {
        int ls = l0 - 3 + i;
        x[i] = (ls >= 0) ? g_proj[((size_t)(b * Ln + ls)) * PROJW + DINn + c] : 0.f;
    }
    #pragma unroll
    for (int j = 0; j < 16; j++) {
        float acc = fmaf(w0, x[j], fmaf(w1, x[j + 1], fmaf(w2, x[j + 2], fmaf(w3, x[j + 3], bias))));
        g_xbc[((size_t)(b * Ln + l0 + j)) * CONVD + c] = siluf(acc);
    }
}

// ---------------- 5) per-chunk SSD via HMMA ----------------
#define KC_B   0
#define KC_C   16384
#define KC_BT  32768
#define KC_XT  49152
#define KC_XDT 57344
#define KC_M   65536
#define KC_ACS 73728
#define KC_DEC 73984
#define KC_SMEM 74496

__global__ __launch_bounds__(256) void k_chunk(const float* __restrict__ dskip) {
    extern __shared__ unsigned char smc[];
    uint32_t sb = smem_u32(smc);
    float* Acs = (float*)(smc + KC_ACS);
    float* Dec = (float*)(smc + KC_DEC);

    int c = blockIdx.x, h = blockIdx.y, b = blockIdx.z;
    int t = threadIdx.x, lane = t & 31, wid = t >> 5;
    size_t rowbase = ((size_t)(b * Ln + c * Qn)) * CONVD;

    for (int i = t; i < 64 * 64; i += 256) {
        int s = i >> 6, cp = i & 63;
        size_t g = rowbase + (size_t)s * CONVD + DINn + cp * 2;
        float b0 = g_xbc[g], b1 = g_xbc[g + 1];
        float c0 = g_xbc[g + Nn], c1 = g_xbc[g + Nn + 1];
        int chunk = cp >> 5;
        uint32_t off = chunk * 8192 + swz128((uint32_t)(s * 128 + (cp & 31) * 4));
        *(uint32_t*)(smc + KC_B + off) = pack2h(b0, b1);
        *(uint32_t*)(smc + KC_C + off) = pack2h(c0, c1);
    }
    for (int i = t; i < 128 * 64; i += 256) {
        int n = i & 127, q = i >> 7;
        float bv = g_xbc[rowbase + (size_t)q * CONVD + DINn + n];
        *(__half*)(smc + KC_BT + swz128((uint32_t)(n * 128 + q * 2))) = __float2half_rn(bv);
    }
    if (t < Qn) Acs[t] = g_a[(size_t)(b * Ln + c * Qn + t) * Hn + h];
    __syncthreads();
    if (t == 0) {
        float r = 0.f;
        for (int i = 0; i < Qn; i++) { r += Acs[i]; Acs[i] = r; }
    }
    __syncthreads();
    if (t < Qn) {
        float aq = Acs[t];
        Dec[t] = expf(Acs[Qn - 1] - aq);
        g_acs[(size_t)(b * Ln + c * Qn + t) * Hn + h] = aq;
        if (t == Qn - 1) g_csum[(size_t)(b * Hn + h) * NCn + c] = aq;
    }
    __syncthreads();
    for (int i = t; i < 64 * 32; i += 256) {
        int p = i & 63, sp = (i >> 6) * 2;
        float x0 = g_xbc[rowbase + (size_t)sp * CONVD + h * Pn + p]
                 * g_dt[(size_t)(b * Ln + c * Qn + sp) * Hn + h];
        float x1 = g_xbc[rowbase + (size_t)(sp + 1) * CONVD + h * Pn + p]
                 * g_dt[(size_t)(b * Ln + c * Qn + sp + 1) * Hn + h];
        uint32_t off = swz128((uint32_t)(p * 128 + sp * 2));
        *(uint32_t*)(smc + KC_XT + off) = pack2h(x0, x1);
        *(uint32_t*)(smc + KC_XDT + off) = pack2h(x0 * Dec[sp], x1 * Dec[sp + 1]);
    }
    __syncthreads();

    int wq = wid & 3, ws = wid >> 2;
    int rA = wq * 16 + (lane & 7) + ((lane >> 3) & 1) * 8;
    int cA = ((lane >> 4) & 1) * 16;
    int rB = ws * 32 + (lane & 7) + ((lane >> 4) & 1) * 8;
    int cB = ((lane >> 3) & 1) * 16;

    // --- M = C @ B^T ---
    float mAcc[4][4];
    #pragma unroll
    for (int i = 0; i < 4; i++)
        #pragma unroll
        for (int j = 0; j < 4; j++) mAcc[i][j] = 0.f;
    #pragma unroll
    for (int ch = 0; ch < 2; ch++) {
        #pragma unroll
        for (int k = 0; k < 4; k++) {
            uint32_t ah[4];
            LDSMX4(ah, sb + KC_C + ch * 8192 + swz128((uint32_t)(rA * 128 + k * 32 + cA)));
            uint32_t bh[2][4];
            #pragma unroll
            for (int ib = 0; ib < 2; ib++)
                LDSMX4(bh[ib], sb + KC_B + ch * 8192 +
                       swz128((uint32_t)((rB + ib * 16) * 128 + k * 32 + cB)));
            #pragma unroll
            for (int ib = 0; ib < 2; ib++)
                #pragma unroll
                for (int hf = 0; hf < 2; hf++)
                    MMA_FP16(mAcc[ib * 2 + hf], ah, bh[ib][2 * hf], bh[ib][2 * hf + 1]);
        }
    }
    {
        int q0 = wq * 16 + (lane >> 2);
        int sc0 = ws * 32 + (lane & 3) * 2;
        #pragma unroll
        for (int nt = 0; nt < 4; nt++) {
            int sc = sc0 + nt * 8;
            #pragma unroll
            for (int r2 = 0; r2 < 2; r2++) {
                int q = q0 + r2 * 8;
                float aq = Acs[q];
                float v0 = (sc <= q)     ? mAcc[nt][r2 * 2 + 0] * expf(aq - Acs[sc])     : 0.f;
                float v1 = (sc + 1 <= q) ? mAcc[nt][r2 * 2 + 1] * expf(aq - Acs[sc + 1]) : 0.f;
                *(uint32_t*)(smc + KC_M + swz128((uint32_t)(q * 128 + sc * 2))) = pack2h(v0, v1);
            }
        }
    }
    __syncthreads();

    // --- Y_diag = Ms @ XdT^T + D_skip*xs ---
    {
        float yAcc[4][4];
        #pragma unroll
        for (int i = 0; i < 4; i++)
            #pragma unroll
            for (int j = 0; j < 4; j++) yAcc[i][j] = 0.f;
        #pragma unroll
        for (int k = 0; k < 4; k++) {
            uint32_t ah[4];
            LDSMX4(ah, sb + KC_M + swz128((uint32_t)(rA * 128 + k * 32 + cA)));
            uint32_t bh[2][4];
            #pragma unroll
            for (int ib = 0; ib < 2; ib++)
                LDSMX4(bh[ib], sb + KC_XT +
                       swz128((uint32_t)((rB + ib * 16) * 128 + k * 32 + cB)));
            #pragma unroll
            for (int ib = 0; ib < 2; ib++)
                #pragma unroll
                for (int hf = 0; hf < 2; hf++)
                    MMA_FP16(yAcc[ib * 2 + hf], ah, bh[ib][2 * hf], bh[ib][2 * hf + 1]);
        }
        float dsk = dskip[h];
        int q0 = wq * 16 + (lane >> 2);
        int p0 = ws * 32 + (lane & 3) * 2;
        #pragma unroll
        for (int nt = 0; nt < 4; nt++) {
            int p = p0 + nt * 8;
            #pragma unroll
            for (int r2 = 0; r2 < 2; r2++) {
                int q = q0 + r2 * 8;
                float2 xs2 = *(const float2*)(g_xbc + rowbase + (size_t)q * CONVD + h * Pn + p);
                float2 o;
                o.x = yAcc[nt][r2 * 2 + 0] + dsk * xs2.x;
                o.y = yAcc[nt][r2 * 2 + 1] + dsk * xs2.y;
                *(float2*)(g_y + ((size_t)(b * Ln + c * Qn + q) * Hn + h) * Pn + p) = o;
            }
        }
    }

    // --- states = XdDT @ BT^T ---
    {
        float sAcc[8][4];
        #pragma unroll
        for (int i = 0; i < 8; i++)
            #pragma unroll
            for (int j = 0; j < 4; j++) sAcc[i][j] = 0.f;
        int rBs = ws * 64 + (lane & 7) + ((lane >> 4) & 1) * 8;
        #pragma unroll
        for (int k = 0; k < 4; k++) {
            uint32_t ah[4];
            LDSMX4(ah, sb + KC_XDT + swz128((uint32_t)(rA * 128 + k * 32 + cA)));
            uint32_t bh[4][4];
            #pragma unroll
            for (int ib = 0; ib < 4; ib++)
                LDSMX4(bh[ib], sb + KC_BT +
                       swz128((uint32_t)((rBs + ib * 16) * 128 + k * 32 + cB)));
            #pragma unroll
            for (int ib = 0; ib < 4; ib++)
                #pragma unroll
                for (int hf = 0; hf < 2; hf++)
                    MMA_FP16(sAcc[ib * 2 + hf], ah, bh[ib][2 * hf], bh[ib][2 * hf + 1]);
        }
        size_t base = ((size_t)(b * Hn + h) * NCn + c) * (Pn * Nn);
        int p0 = wq * 16 + (lane >> 2);
        int n0 = ws * 64 + (lane & 3) * 2;
        #pragma unroll
        for (int nt = 0; nt < 8; nt++) {
            int n = n0 + nt * 8;
            #pragma unroll
            for (int r2 = 0; r2 < 2; r2++) {
                int p = p0 + r2 * 8;
                float2 o = make_float2(sAcc[nt][r2 * 2 + 0], sAcc[nt][r2 * 2 + 1]);
                *(float2*)(g_states + base + (size_t)p * Nn + n) = o;
            }
        }
    }
}

// ---------------- 6) chunk-level scan ----------------
__global__ __launch_bounds__(256) void k_scan() {
    int bh = blockIdx.x;
    int e0 = blockIdx.y * 512 + threadIdx.x;
    float S[2];
    S[0] = 0.f; S[1] = 0.f;
    for (int c = 0; c < NCn; c++) {
        size_t base = ((size_t)bh * NCn + c) * (Pn * Nn);
        g_statein[base + e0] = S[0];
        g_statein[base + e0 + 256] = S[1];
        float f = expf(g_csum[(size_t)bh * NCn + c]);
        S[0] = fmaf(f, S[0], g_states[base + e0]);
        S[1] = fmaf(f, S[1], g_states[base + e0 + 256]);
    }
}

// ---------------- 7) Y_off via HMMA ----------------
#define KY_C   0
#define KY_S   16384
#define KY_EQ  32768
#define KY_SMEM 33280

__global__ __launch_bounds__(256) void k_yoff() {
    extern __shared__ unsigned char smy[];
    uint32_t sb = smem_u32(smy);
    float* Eq = (float*)(smy + KY_EQ);

    int c = blockIdx.x, h = blockIdx.y, b = blockIdx.z;
    int t = threadIdx.x, lane = t & 31, wid = t >> 5;
    size_t rowbase = ((size_t)(b * Ln + c * Qn)) * CONVD;
    size_t sbase = ((size_t)(b * Hn + h) * NCn + c) * (Pn * Nn);

    for (int i = t; i < 64 * 64; i += 256) {
        int q = i >> 6, cp = i & 63;
        size_t g = rowbase + (size_t)q * CONVD + DINn + Nn + cp * 2;
        int chunk = cp >> 5;
        uint32_t off = chunk * 8192 + swz128((uint32_t)(q * 128 + (cp & 31) * 4));
        *(uint32_t*)(smy + KY_C + off) = pack2h(g_xbc[g], g_xbc[g + 1]);
    }
    for (int i = t; i < 64 * 64; i += 256) {
        int p = i >> 6, np = i & 63;
        const float* sp = g_statein + sbase + (size_t)p * Nn + np * 2;
        int chunk = np >> 5;
        uint32_t off = chunk * 8192 + swz128((uint32_t)(p * 128 + (np & 31) * 4));
        *(uint32_t*)(smy + KY_S + off) = pack2h(sp[0], sp[1]);
    }
    if (t < Qn)
        Eq[t] = expf(g_acs[(size_t)(b * Ln + c * Qn + t) * Hn + h]);
    __syncthreads();

    int wq = wid & 3, ws = wid >> 2;
    int rA = wq * 16 + (lane & 7) + ((lane >> 3) & 1) * 8;
    int cA = ((lane >> 4) & 1) * 16;
    int rB = ws * 32 + (lane & 7) + ((lane >> 4) & 1) * 8;
    int cB = ((lane >> 3) & 1) * 16;

    float acc[4][4];
    #pragma unroll
    for (int i = 0; i < 4; i++)
        #pragma unroll
        for (int j = 0; j < 4; j++) acc[i][j] = 0.f;
    #pragma unroll
    for (int ch = 0; ch < 2; ch++) {
        #pragma unroll
        for (int k = 0; k < 4; k++) {
            uint32_t ah[4];
            LDSMX4(ah, sb + KY_C + ch * 8192 + swz128((uint32_t)(rA * 128 + k * 32 + cA)));
            uint32_t bh[2][4];
            #pragma unroll
            for (int ib = 0; ib < 2; ib++)
                LDSMX4(bh[ib], sb + KY_S + ch * 8192 +
                       swz128((uint32_t)((rB + ib * 16) * 128 + k * 32 + cB)));
            #pragma unroll
            for (int ib = 0; ib < 2; ib++)
                #pragma unroll
                for (int hf = 0; hf < 2; hf++)
                    MMA_FP16(acc[ib * 2 + hf], ah, bh[ib][2 * hf], bh[ib][2 * hf + 1]);
        }
    }
    int q0 = wq * 16 + (lane >> 2);
    int p0 = ws * 32 + (lane & 3) * 2;
    #pragma unroll
    for (int nt = 0; nt < 4; nt++) {
        int p = p0 + nt * 8;
        #pragma unroll
        for (int r2 = 0; r2 < 2; r2++) {
            int q = q0 + r2 * 8;
            float e = Eq[q];
            float* dst = g_y + ((size_t)(b * Ln + c * Qn + q) * Hn + h) * Pn + p;
            float2 cur = *(float2*)dst;
            cur.x += e * acc[nt][r2 * 2 + 0];
            cur.y += e * acc[nt][r2 * 2 + 1];
            *(float2*)dst = cur;
        }
    }
}

// ---------------- 8) gated rmsnorm -> fp16 A tiles ----------------
__global__ __launch_bounds__(256) void k_gatenorm_split(
    const float* __restrict__ gw, unsigned char* __restrict__ Af) {
    size_t row = blockIdx.x;
    int t = threadIdx.x;
    const float4* py = (const float4*)(g_y + row * DINn);
    const float4* pz = (const float4*)(g_proj + row * PROJW);
    float v[16];
    float ss = 0.f;
    #pragma unroll
    for (int i = 0; i < 4; i++) {
        float4 y4 = py[t * 4 + i];
        float4 z4 = pz[t * 4 + i];
        float x0 = y4.x * siluf(z4.x);
        float x1 = y4.y * siluf(z4.y);
        float x2 = y4.z * siluf(z4.z);
        float x3 = y4.w * siluf(z4.w);
        v[i * 4 + 0] = x0; v[i * 4 + 1] = x1; v[i * 4 + 2] = x2; v[i * 4 + 3] = x3;
        ss += x0 * x0 + x1 * x1 + x2 * x2 + x3 * x3;
    }
    float tot = block_reduce_sum(ss);
    float inv = rsqrtf(tot / (float)DINn + EPSf);
    int mt = (int)(row >> 7), r = (int)(row & 127);
    size_t tb = (size_t)mt * NCH2 * A_CH;
    #pragma unroll
    for (int j = 0; j < 8; j++) {
        int k = t * 16 + j * 2;
        uint32_t u = pack2h(v[j * 2] * inv * gw[k], v[j * 2 + 1] * inv * gw[k + 1]);
        int kc = k >> 6, cc = k & 63;
        size_t off = tb + (size_t)kc * A_CH + swz128((uint32_t)(r * 128 + cc * 2));
        *(uint32_t*)(Af + off) = u;
    }
}

// ---------------- launch ----------------
extern "C" void kernel_launch(void* const* d_in, const int* in_sizes, int n_in,
                              void* d_out, int out_size) {
    const float* hs   = (const float*)d_in[0];
    const float* res  = (const float*)d_in[1];
    const float* nw   = (const float*)d_in[2];
    const float* ipw  = (const float*)d_in[3];
    const float* cw   = (const float*)d_in[4];
    const float* cb   = (const float*)d_in[5];
    const float* alog = (const float*)d_in[6];
    const float* dtb  = (const float*)d_in[7];
    const float* dsk  = (const float*)d_in[8];
    const float* gnw  = (const float*)d_in[9];
    const float* opw  = (const float*)d_in[10];
    float* out = (float*)d_out;

    void *pproj, *pAf, *pBf, *pyfb;
    cudaGetSymbolAddress(&pproj, g_proj);
    cudaGetSymbolAddress(&pAf, g_Af);
    cudaGetSymbolAddress(&pBf, g_Bf);
    cudaGetSymbolAddress(&pyfb, g_y);

    float* resid_ptr = ((size_t)out_size >= 2ull * BLn * Dn)
                           ? out + (size_t)BLn * Dn
                           : (float*)pyfb;

    const int SMEM_GEMM = 1024 + NSTAGE * (16384 + 32768) + 64;
    cudaFuncSetAttribute(k_chunk, cudaFuncAttributeMaxDynamicSharedMemorySize, KC_SMEM);
    cudaFuncSetAttribute(k_yoff,  cudaFuncAttributeMaxDynamicSharedMemorySize, KY_SMEM);
    cudaFuncSetAttribute(gemm_mma_fp16, cudaFuncAttributeMaxDynamicSharedMemorySize, SMEM_GEMM);

    k_add_rmsnorm_split<<<BLn, 256>>>(hs, res, nw, resid_ptr, (unsigned char*)pAf);
    k_dtproj<<<BLn / 64, 256>>>(ipw, dtb, alog);

    {
        dim3 grid(PROJW / 32, Dn / 64);
        k_splitB<<<grid, 256>>>(ipw, (unsigned char*)pBf, PROJW, NCH1);
    }
    {
        dim3 grid(NT1, MTil);   // 33 tiles: z + xBC columns only
        gemm_mma_fp16<<<grid, 512, SMEM_GEMM>>>(
            (const unsigned char*)pAf, (const unsigned char*)pBf,
            (float*)pproj, PROJW, NCH1);
    }

    k_conv2<<<Bn * 128 * 17, 256>>>(cw, cb);

    {
        dim3 grid(NCn, Hn, Bn);
        k_chunk<<<grid, 256, KC_SMEM>>>(dsk);
    }
    {
        dim3 grid(Bn * Hn, 16);
        k_scan<<<grid, 256>>>();
    }
    {
        dim3 grid(NCn, Hn, Bn);
        k_yoff<<<grid, 256, KY_SMEM>>>();
    }

    k_gatenorm_split<<<BLn, 256>>>(gnw, (unsigned char*)pAf);

    {
        dim3 grid(Dn / 32, DINn / 64);
        k_splitB<<<grid, 256>>>(opw, (unsigned char*)pBf, Dn, NCH2);
    }
    {
        dim3 grid(Dn / 256, MTil);
        gemm_mma_fp16<<<grid, 512, SMEM_GEMM>>>(
            (const unsigned char*)pAf, (const unsigned char*)pBf,
            out, Dn, NCH2);
    }
}

// round 14
// speedup vs baseline: 2.2630x; 1.0633x over previous
#include <cuda_runtime.h>
#include <cuda_fp16.h>
#include <math.h>
#include <stdint.h>

// ---------------- problem constants ----------------
#define Bn    2
#define Ln    2048
#define Dn    2048
#define DINn  4096
#define Nn    128
#define Hn    64
#define Pn    64
#define Kc    4
#define CONVD 4352            // DIN + 2*G*N
#define Qn    64
#define NCn   32
#define PROJW 8512            // 2*DIN + 2*G*N + H
#define DTOFF 8448            // DIN + CONVD
#define BLn   (Bn*Ln)         // 4096
#define EPSf  1e-5f

// GEMM tiling: 128(M) x 256(N) block tile, BK=64, 512 threads, fp16 single-pass
#define A_CH  16384
#define B_CH  32768
#define NSTAGE 4

#define NCH1  32
#define NT1   33              // 33*256 = 8448: z + xBC only (dt handled by k_dtproj)
#define NTB1  34
#define NCH2  64
#define MTil  32

// ---------------- scratch ----------------
__device__ float g_h[(size_t)BLn*Dn];
__device__ float g_proj[(size_t)BLn*PROJW];
__device__ __half g_xbc[(size_t)BLn*CONVD];          // fp16 now
__device__ float g_dt[(size_t)BLn*Hn];
__device__ float g_a[(size_t)BLn*Hn];
__device__ float g_acs[(size_t)BLn*Hn];
__device__ float g_csum[(size_t)Bn*Hn*NCn];
__device__ float g_states[(size_t)Bn*Hn*NCn*Pn*Nn];
__device__ __align__(16) unsigned char g_statein[(size_t)Bn*Hn*NCn*16384]; // fp16 swizzled tiles
__device__ float g_y[(size_t)BLn*DINn];

__device__ __align__(1024) unsigned char g_Af[(size_t)MTil*NCH2*A_CH];
__device__ __align__(1024) unsigned char g_Bf[(size_t)NTB1*NCH1*B_CH];

// ---------------- PTX helpers ----------------
__device__ __forceinline__ uint32_t smem_u32(const void* p) {
    uint32_t a;
    asm("{ .reg .u64 t; cvta.to.shared.u64 t, %1; cvt.u32.u64 %0, t; }" : "=r"(a) : "l"(p));
    return a;
}
__device__ __forceinline__ uint32_t swz128(uint32_t o) { return o ^ ((o >> 3) & 0x70); }

#define MBAR_INIT(a, c) \
    asm volatile("mbarrier.init.shared.b64 [%0], %1;" :: "r"(a), "r"(c) : "memory")
#define MBAR_EXPECT_TX(a, b) \
    asm volatile("mbarrier.arrive.expect_tx.shared.b64 _, [%0], %1;" :: "r"(a), "r"(b) : "memory")
#define MBAR_WAIT(a, ph) do { \
    uint32_t _m = (a); uint32_t _p = (ph); uint32_t _d; \
    asm volatile("{\n\t.reg .pred p;\n\t" \
        "mbarrier.try_wait.parity.acquire.cta.shared::cta.b64 p, [%1], %2;\n\t" \
        "selp.b32 %0, 1, 0, p;\n\t}" : "=r"(_d) : "r"(_m), "r"(_p) : "memory"); \
    if (!_d) { \
        asm volatile("{\n\t.reg .pred P1;\n\t" \
            "WL_%=:\n\t" \
            "mbarrier.try_wait.parity.acquire.cta.shared::cta.b64 P1, [%0], %1, 0x989680;\n\t" \
            "@P1 bra.uni WD_%=;\n\t" \
            "bra.uni WL_%=;\n\t" \
            "WD_%=:\n\t}" :: "r"(_m), "r"(_p) : "memory"); \
    } \
} while (0)

#define BULK_LD(sa, gp, bytes, mb) \
    asm volatile("cp.async.bulk.shared::cluster.global.mbarrier::complete_tx::bytes [%0], [%1], %2, [%3];" \
        :: "r"(sa), "l"(gp), "r"(bytes), "r"(mb) : "memory")

#define LDSMX4(r, addr) \
    asm volatile("ldmatrix.sync.aligned.m8n8.x4.shared.b16 {%0,%1,%2,%3}, [%4];" \
        : "=r"((r)[0]), "=r"((r)[1]), "=r"((r)[2]), "=r"((r)[3]) : "r"(addr))

#define MMA_FP16(d, a, b0, b1) \
    asm volatile("mma.sync.aligned.m16n8k16.row.col.f32.f16.f16.f32 " \
        "{%0,%1,%2,%3}, {%4,%5,%6,%7}, {%8,%9}, {%0,%1,%2,%3};" \
        : "+f"((d)[0]), "+f"((d)[1]), "+f"((d)[2]), "+f"((d)[3]) \
        : "r"((a)[0]), "r"((a)[1]), "r"((a)[2]), "r"((a)[3]), "r"(b0), "r"(b1))

// ---------------- misc helpers ----------------
__device__ __forceinline__ float block_reduce_sum(float v) {
    __shared__ float red[32];
    int lane = threadIdx.x & 31, wid = threadIdx.x >> 5;
    #pragma unroll
    for (int o = 16; o; o >>= 1) v += __shfl_down_sync(0xffffffffu, v, o);
    if (lane == 0) red[wid] = v;
    __syncthreads();
    v = (threadIdx.x < (blockDim.x >> 5)) ? red[threadIdx.x] : 0.f;
    if (wid == 0) {
        #pragma unroll
        for (int o = 16; o; o >>= 1) v += __shfl_down_sync(0xffffffffu, v, o);
        if (lane == 0) red[0] = v;
    }
    __syncthreads();
    return red[0];
}
__device__ __forceinline__ float siluf(float x) { return x / (1.f + expf(-x)); }

__device__ __forceinline__ uint32_t pack2h(float x0, float x1) {
    __half h0 = __float2half_rn(x0);
    __half h1 = __float2half_rn(x1);
    return ((uint32_t)__half_as_ushort(h1) << 16) | __half_as_ushort(h0);
}

// ---------------- 1) resid + rmsnorm -> fp32 g_h + fp16 A tiles ----------------
__global__ __launch_bounds__(256) void k_add_rmsnorm_split(
    const float* __restrict__ hs, const float* __restrict__ res,
    const float* __restrict__ w, float* __restrict__ resid_out,
    unsigned char* __restrict__ Af) {
    size_t row = blockIdx.x;
    int t = threadIdx.x;
    const float4* ph = (const float4*)(hs + row * Dn);
    const float4* pr = (const float4*)(res + row * Dn);
    float4* po = (float4*)(resid_out + row * Dn);
    float v[8];
    float ss = 0.f;
    #pragma unroll
    for (int i = 0; i < 2; i++) {
        float4 a = ph[t * 2 + i], b = pr[t * 2 + i];
        float4 x = make_float4(a.x + b.x, a.y + b.y, a.z + b.z, a.w + b.w);
        po[t * 2 + i] = x;
        v[i * 4 + 0] = x.x; v[i * 4 + 1] = x.y; v[i * 4 + 2] = x.z; v[i * 4 + 3] = x.w;
        ss += x.x * x.x + x.y * x.y + x.z * x.z + x.w * x.w;
    }
    float tot = block_reduce_sum(ss);
    float inv = rsqrtf(tot / (float)Dn + EPSf);
    int mt = (int)(row >> 7), r = (int)(row & 127);
    size_t tb = (size_t)mt * NCH1 * A_CH;
    float4* gh = (float4*)(g_h + row * Dn);
    #pragma unroll
    for (int i = 0; i < 2; i++) {
        float4 x = make_float4(v[i*4]*inv*w[t*8+i*4], v[i*4+1]*inv*w[t*8+i*4+1],
                               v[i*4+2]*inv*w[t*8+i*4+2], v[i*4+3]*inv*w[t*8+i*4+3]);
        gh[t * 2 + i] = x;
        v[i*4] = x.x; v[i*4+1] = x.y; v[i*4+2] = x.z; v[i*4+3] = x.w;
    }
    #pragma unroll
    for (int j = 0; j < 4; j++) {
        int k = t * 8 + j * 2;
        uint32_t u = pack2h(v[j * 2], v[j * 2 + 1]);
        int kc = k >> 6, c = k & 63;
        size_t off = tb + (size_t)kc * A_CH + swz128((uint32_t)(r * 128 + c * 2));
        *(uint32_t*)(Af + off) = u;
    }
}

// ---------------- weight transpose to fp16 ----------------
__global__ __launch_bounds__(256) void k_splitB(
    const float* __restrict__ W, unsigned char* __restrict__ Bf, int Nreal, int nch) {
    __shared__ float tile[64][33];
    int kb = blockIdx.y * 64;
    int n0 = blockIdx.x * 32;
    int t = threadIdx.x;
    int tx = t & 31, ty = t >> 5;
    #pragma unroll
    for (int i = 0; i < 8; i++) {
        int k = ty + i * 8;
        tile[k][tx] = W[(size_t)(kb + k) * Nreal + n0 + tx];
    }
    __syncthreads();
    int kc = kb >> 6;
    #pragma unroll
    for (int j = 0; j < 4; j++) {
        int nl = ty * 4 + j;
        int n = n0 + nl;
        uint32_t u = pack2h(tile[tx * 2][nl], tile[tx * 2 + 1][nl]);
        int nt = n >> 8, r = n & 255;
        size_t base = ((size_t)(nt * nch + kc)) * B_CH;
        size_t off = base + swz128((uint32_t)(r * 128 + tx * 4));
        *(uint32_t*)(Bf + off) = u;
    }
}

// ---------------- fp16 GEMM: 4-stage, paired-chunk consumption (R13-proven) ----------------
__global__ __launch_bounds__(512) void gemm_mma_fp16(
    const unsigned char* __restrict__ Af, const unsigned char* __restrict__ Bf,
    float* __restrict__ C, int Nreal, int nch) {
    constexpr int STGB = 16384 + 32768;
    extern __shared__ unsigned char smg[];
    uint32_t sb = (smem_u32(smg) + 1023) & ~1023u;
    uint32_t ctrl = sb + NSTAGE * STGB;
    int t = threadIdx.x, lane = t & 31, wid = t >> 5;
    int bx = blockIdx.x, by = blockIdx.y;

    if (t == 0) {
        MBAR_INIT(ctrl + 0, 1); MBAR_INIT(ctrl + 8, 1);
        MBAR_INIT(ctrl + 16, 1); MBAR_INIT(ctrl + 24, 1);
    }
    __syncthreads();

    const unsigned char* Ap = Af + (size_t)by * nch * A_CH;
    const unsigned char* Bp = Bf + (size_t)bx * nch * B_CH;

    int wm = wid & 1, wn = wid >> 1;
    int rowA = wm * 64 + (lane & 7) + ((lane >> 3) & 1) * 8;
    int colA = ((lane >> 4) & 1) * 16;
    int rowB = wn * 32 + (lane & 7) + ((lane >> 4) & 1) * 8;
    int colB = ((lane >> 3) & 1) * 16;

    float acc[4][4][4];
    #pragma unroll
    for (int i = 0; i < 4; i++)
        #pragma unroll
        for (int j = 0; j < 4; j++)
            #pragma unroll
            for (int q = 0; q < 4; q++) acc[i][j][q] = 0.f;

    if (t == 0) {
        #pragma unroll
        for (int pc = 0; pc < 4; pc++) {
            MBAR_EXPECT_TX(ctrl + pc * 8, STGB);
            BULK_LD(sb + pc * STGB + 0,     Ap + (size_t)pc * A_CH, A_CH, ctrl + pc * 8);
            BULK_LD(sb + pc * STGB + 16384, Bp + (size_t)pc * B_CH, B_CH, ctrl + pc * 8);
        }
    }
    int ph[NSTAGE] = {0, 0, 0, 0};
    for (int kc = 0; kc < nch; kc += 2) {
        #pragma unroll
        for (int half = 0; half < 2; half++) {
            int slot = (kc + half) % NSTAGE;
            MBAR_WAIT(ctrl + slot * 8, ph[slot]);
            ph[slot] ^= 1;
            uint32_t s = sb + slot * STGB;
            uint32_t sA = s, sB = s + 16384;
            #pragma unroll
            for (int k = 0; k < 4; k++) {
                uint32_t bh[2][4];
                #pragma unroll
                for (int ib = 0; ib < 2; ib++) {
                    uint32_t off = swz128((uint32_t)((rowB + ib * 16) * 128 + k * 32 + colB));
                    LDSMX4(bh[ib], sB + off);
                }
                #pragma unroll
                for (int im = 0; im < 4; im++) {
                    uint32_t ah[4];
                    uint32_t off = swz128((uint32_t)((rowA + im * 16) * 128 + k * 32 + colA));
                    LDSMX4(ah, sA + off);
                    #pragma unroll
                    for (int ib = 0; ib < 2; ib++)
                        #pragma unroll
                        for (int hf = 0; hf < 2; hf++)
                            MMA_FP16(acc[im][ib * 2 + hf], ah, bh[ib][2 * hf], bh[ib][2 * hf + 1]);
                }
            }
        }
        __syncthreads();
        if (t == 0) {
            #pragma unroll
            for (int half = 0; half < 2; half++) {
                int nc = kc + 4 + half;
                if (nc < nch) {
                    int ns = nc % NSTAGE;
                    uint32_t d = sb + ns * STGB;
                    uint32_t mb = ctrl + ns * 8;
                    MBAR_EXPECT_TX(mb, STGB);
                    BULK_LD(d + 0,     Ap + (size_t)nc * A_CH, A_CH, mb);
                    BULK_LD(d + 16384, Bp + (size_t)nc * B_CH, B_CH, mb);
                }
            }
        }
    }

    int mBase = by * 128 + wm * 64;
    int nBase = bx * 256 + wn * 32;
    #pragma unroll
    for (int im = 0; im < 4; im++) {
        #pragma unroll
        for (int in = 0; in < 4; in++) {
            int r = mBase + im * 16 + (lane >> 2);
            int c = nBase + in * 8 + (lane & 3) * 2;
            if (c < Nreal) {
                float2 v0 = make_float2(acc[im][in][0], acc[im][in][1]);
                float2 v1 = make_float2(acc[im][in][2], acc[im][in][3]);
                *(float2*)(C + (size_t)r * Nreal + c) = v0;
                *(float2*)(C + (size_t)(r + 8) * Nreal + c) = v1;
            }
        }
    }
}

// ---------------- exact fp32 skinny GEMM for dt columns + softplus ----------------
__global__ __launch_bounds__(256) void k_dtproj(
    const float* __restrict__ ipw, const float* __restrict__ dtb,
    const float* __restrict__ alog) {
    __shared__ float sh[64][68];
    __shared__ float sw[64][68];
    int m0 = blockIdx.x * 64;
    int t = threadIdx.x;
    int tm = t >> 4, tn = t & 15;
    float acc[4][4];
    #pragma unroll
    for (int i = 0; i < 4; i++)
        #pragma unroll
        for (int j = 0; j < 4; j++) acc[i][j] = 0.f;

    for (int kb = 0; kb < Dn; kb += 64) {
        #pragma unroll
        for (int i = 0; i < 16; i++) {
            int idx = t + i * 256;
            int m = idx >> 6, kk = idx & 63;
            sh[kk][m] = g_h[(size_t)(m0 + m) * Dn + kb + kk];
        }
        #pragma unroll
        for (int i = 0; i < 16; i++) {
            int idx = t + i * 256;
            int kk = idx >> 6, h = idx & 63;
            sw[kk][h] = ipw[(size_t)(kb + kk) * PROJW + DTOFF + h];
        }
        __syncthreads();
        #pragma unroll 8
        for (int kk = 0; kk < 64; kk++) {
            float4 ar = *(const float4*)&sh[kk][tm * 4];
            float4 br = *(const float4*)&sw[kk][tn * 4];
            float a4[4] = {ar.x, ar.y, ar.z, ar.w};
            float b4[4] = {br.x, br.y, br.z, br.w};
            #pragma unroll
            for (int i = 0; i < 4; i++)
                #pragma unroll
                for (int j = 0; j < 4; j++) acc[i][j] = fmaf(a4[i], b4[j], acc[i][j]);
        }
        __syncthreads();
    }
    #pragma unroll
    for (int i = 0; i < 4; i++) {
        int m = m0 + tm * 4 + i;
        #pragma unroll
        for (int j = 0; j < 4; j++) {
            int h = tn * 4 + j;
            float x = acc[i][j] + dtb[h];
            float sp = (x > 20.f) ? x : log1pf(expf(x));
            g_dt[(size_t)m * Hn + h] = sp;
            g_a[(size_t)m * Hn + h] = -expf(alog[h]) * sp;
        }
    }
}

// ---------------- 3) causal depthwise conv -> fp16 g_xbc ----------------
__global__ __launch_bounds__(256) void k_conv2(
    const float* __restrict__ cw, const float* __restrict__ cb) {
    int bid = blockIdx.x;
    int c = (bid % 17) * 256 + threadIdx.x;
    int lblk = (bid / 17) & 127;
    int b = bid / (17 * 128);
    int l0 = lblk * 16;
    float w0 = cw[c * 4 + 0], w1 = cw[c * 4 + 1], w2 = cw[c * 4 + 2], w3 = cw[c * 4 + 3];
    float bias = cb[c];
    float x[19];
    #pragma unroll
    for (int i = 0; i < 19; i++) {
        int ls = l0 - 3 + i;
        x[i] = (ls >= 0) ? g_proj[((size_t)(b * Ln + ls)) * PROJW + DINn + c] : 0.f;
    }
    #pragma unroll
    for (int j = 0; j < 16; j++) {
        float acc = fmaf(w0, x[j], fmaf(w1, x[j + 1], fmaf(w2, x[j + 2], fmaf(w3, x[j + 3], bias))));
        g_xbc[((size_t)(b * Ln + l0 + j)) * CONVD + c] = __float2half_rn(siluf(acc));
    }
}

// ---------------- 5) per-chunk SSD via HMMA (fp16 g_xbc) ----------------
#define KC_B   0
#define KC_C   16384
#define KC_BT  32768
#define KC_XT  49152
#define KC_XDT 57344
#define KC_M   65536
#define KC_ACS 73728
#define KC_DEC 73984
#define KC_SMEM 74496

__global__ __launch_bounds__(256) void k_chunk(const float* __restrict__ dskip) {
    extern __shared__ unsigned char smc[];
    uint32_t sb = smem_u32(smc);
    float* Acs = (float*)(smc + KC_ACS);
    float* Dec = (float*)(smc + KC_DEC);

    int c = blockIdx.x, h = blockIdx.y, b = blockIdx.z;
    int t = threadIdx.x, lane = t & 31, wid = t >> 5;
    size_t rowbase = ((size_t)(b * Ln + c * Qn)) * CONVD;

    // B/C tiles: raw uint32 (half2) copies
    for (int i = t; i < 64 * 64; i += 256) {
        int s = i >> 6, cp = i & 63;
        size_t g = rowbase + (size_t)s * CONVD + DINn + cp * 2;
        uint32_t bu = *(const uint32_t*)(g_xbc + g);
        uint32_t cu = *(const uint32_t*)(g_xbc + g + Nn);
        int chunk = cp >> 5;
        uint32_t off = chunk * 8192 + swz128((uint32_t)(s * 128 + (cp & 31) * 4));
        *(uint32_t*)(smc + KC_B + off) = bu;
        *(uint32_t*)(smc + KC_C + off) = cu;
    }
    for (int i = t; i < 128 * 64; i += 256) {
        int n = i & 127, q = i >> 7;
        *(__half*)(smc + KC_BT + swz128((uint32_t)(n * 128 + q * 2))) =
            g_xbc[rowbase + (size_t)q * CONVD + DINn + n];
    }
    if (t < Qn) Acs[t] = g_a[(size_t)(b * Ln + c * Qn + t) * Hn + h];
    __syncthreads();
    if (t == 0) {
        float r = 0.f;
        for (int i = 0; i < Qn; i++) { r += Acs[i]; Acs[i] = r; }
    }
    __syncthreads();
    if (t < Qn) {
        float aq = Acs[t];
        Dec[t] = expf(Acs[Qn - 1] - aq);
        g_acs[(size_t)(b * Ln + c * Qn + t) * Hn + h] = aq;
        if (t == Qn - 1) g_csum[(size_t)(b * Hn + h) * NCn + c] = aq;
    }
    __syncthreads();
    for (int i = t; i < 64 * 32; i += 256) {
        int p = i & 63, sp = (i >> 6) * 2;
        float x0 = __half2float(g_xbc[rowbase + (size_t)sp * CONVD + h * Pn + p])
                 * g_dt[(size_t)(b * Ln + c * Qn + sp) * Hn + h];
        float x1 = __half2float(g_xbc[rowbase + (size_t)(sp + 1) * CONVD + h * Pn + p])
                 * g_dt[(size_t)(b * Ln + c * Qn + sp + 1) * Hn + h];
        uint32_t off = swz128((uint32_t)(p * 128 + sp * 2));
        *(uint32_t*)(smc + KC_XT + off) = pack2h(x0, x1);
        *(uint32_t*)(smc + KC_XDT + off) = pack2h(x0 * Dec[sp], x1 * Dec[sp + 1]);
    }
    __syncthreads();

    int wq = wid & 3, ws = wid >> 2;
    int rA = wq * 16 + (lane & 7) + ((lane >> 3) & 1) * 8;
    int cA = ((lane >> 4) & 1) * 16;
    int rB = ws * 32 + (lane & 7) + ((lane >> 4) & 1) * 8;
    int cB = ((lane >> 3) & 1) * 16;

    // --- M = C @ B^T ---
    float mAcc[4][4];
    #pragma unroll
    for (int i = 0; i < 4; i++)
        #pragma unroll
        for (int j = 0; j < 4; j++) mAcc[i][j] = 0.f;
    #pragma unroll
    for (int ch = 0; ch < 2; ch++) {
        #pragma unroll
        for (int k = 0; k < 4; k++) {
            uint32_t ah[4];
            LDSMX4(ah, sb + KC_C + ch * 8192 + swz128((uint32_t)(rA * 128 + k * 32 + cA)));
            uint32_t bh[2][4];
            #pragma unroll
            for (int ib = 0; ib < 2; ib++)
                LDSMX4(bh[ib], sb + KC_B + ch * 8192 +
                       swz128((uint32_t)((rB + ib * 16) * 128 + k * 32 + cB)));
            #pragma unroll
            for (int ib = 0; ib < 2; ib++)
                #pragma unroll
                for (int hf = 0; hf < 2; hf++)
                    MMA_FP16(mAcc[ib * 2 + hf], ah, bh[ib][2 * hf], bh[ib][2 * hf + 1]);
        }
    }
    {
        int q0 = wq * 16 + (lane >> 2);
        int sc0 = ws * 32 + (lane & 3) * 2;
        #pragma unroll
        for (int nt = 0; nt < 4; nt++) {
            int sc = sc0 + nt * 8;
            #pragma unroll
            for (int r2 = 0; r2 < 2; r2++) {
                int q = q0 + r2 * 8;
                float aq = Acs[q];
                float v0 = (sc <= q)     ? mAcc[nt][r2 * 2 + 0] * expf(aq - Acs[sc])     : 0.f;
                float v1 = (sc + 1 <= q) ? mAcc[nt][r2 * 2 + 1] * expf(aq - Acs[sc + 1]) : 0.f;
                *(uint32_t*)(smc + KC_M + swz128((uint32_t)(q * 128 + sc * 2))) = pack2h(v0, v1);
            }
        }
    }
    __syncthreads();

    // --- Y_diag = Ms @ XdT^T + D_skip*xs ---
    {
        float yAcc[4][4];
        #pragma unroll
        for (int i = 0; i < 4; i++)
            #pragma unroll
            for (int j = 0; j < 4; j++) yAcc[i][j] = 0.f;
        #pragma unroll
        for (int k = 0; k < 4; k++) {
            uint32_t ah[4];
            LDSMX4(ah, sb + KC_M + swz128((uint32_t)(rA * 128 + k * 32 + cA)));
            uint32_t bh[2][4];
            #pragma unroll
            for (int ib = 0; ib < 2; ib++)
                LDSMX4(bh[ib], sb + KC_XT +
                       swz128((uint32_t)((rB + ib * 16) * 128 + k * 32 + cB)));
            #pragma unroll
            for (int ib = 0; ib < 2; ib++)
                #pragma unroll
                for (int hf = 0; hf < 2; hf++)
                    MMA_FP16(yAcc[ib * 2 + hf], ah, bh[ib][2 * hf], bh[ib][2 * hf + 1]);
        }
        float dsk = dskip[h];
        int q0 = wq * 16 + (lane >> 2);
        int p0 = ws * 32 + (lane & 3) * 2;
        #pragma unroll
        for (int nt = 0; nt < 4; nt++) {
            int p = p0 + nt * 8;
            #pragma unroll
            for (int r2 = 0; r2 < 2; r2++) {
                int q = q0 + r2 * 8;
                __half2 xsh = *(const __half2*)(g_xbc + rowbase + (size_t)q * CONVD + h * Pn + p);
                float2 xs2 = __half22float2(xsh);
                float2 o;
                o.x = yAcc[nt][r2 * 2 + 0] + dsk * xs2.x;
                o.y = yAcc[nt][r2 * 2 + 1] + dsk * xs2.y;
                *(float2*)(g_y + ((size_t)(b * Ln + c * Qn + q) * Hn + h) * Pn + p) = o;
            }
        }
    }

    // --- states = XdDT @ BT^T ---
    {
        float sAcc[8][4];
        #pragma unroll
        for (int i = 0; i < 8; i++)
            #pragma unroll
            for (int j = 0; j < 4; j++) sAcc[i][j] = 0.f;
        int rBs = ws * 64 + (lane & 7) + ((lane >> 4) & 1) * 8;
        #pragma unroll
        for (int k = 0; k < 4; k++) {
            uint32_t ah[4];
            LDSMX4(ah, sb + KC_XDT + swz128((uint32_t)(rA * 128 + k * 32 + cA)));
            uint32_t bh[4][4];
            #pragma unroll
            for (int ib = 0; ib < 4; ib++)
                LDSMX4(bh[ib], sb + KC_BT +
                       swz128((uint32_t)((rBs + ib * 16) * 128 + k * 32 + cB)));
            #pragma unroll
            for (int ib = 0; ib < 4; ib++)
                #pragma unroll
                for (int hf = 0; hf < 2; hf++)
                    MMA_FP16(sAcc[ib * 2 + hf], ah, bh[ib][2 * hf], bh[ib][2 * hf + 1]);
        }
        size_t base = ((size_t)(b * Hn + h) * NCn + c) * (Pn * Nn);
        int p0 = wq * 16 + (lane >> 2);
        int n0 = ws * 64 + (lane & 3) * 2;
        #pragma unroll
        for (int nt = 0; nt < 8; nt++) {
            int n = n0 + nt * 8;
            #pragma unroll
            for (int r2 = 0; r2 < 2; r2++) {
                int p = p0 + r2 * 8;
                float2 o = make_float2(sAcc[nt][r2 * 2 + 0], sAcc[nt][r2 * 2 + 1]);
                *(float2*)(g_states + base + (size_t)p * Nn + n) = o;
            }
        }
    }
}

// ---------------- 6) chunk-level scan -> fp16 swizzled statein tiles ----------------
__global__ __launch_bounds__(256) void k_scan() {
    int bh = blockIdx.x;
    int idx = blockIdx.y * 256 + threadIdx.x;   // 0..4095 over (p, np)
    int p = idx >> 6, np = idx & 63;
    int chn = np >> 5;
    uint32_t soff = chn * 8192 + swz128((uint32_t)(p * 128 + (np & 31) * 4));
    float S0 = 0.f, S1 = 0.f;
    for (int c = 0; c < NCn; c++) {
        size_t basef = ((size_t)bh * NCn + c) * (Pn * Nn);
        size_t baseb = ((size_t)bh * NCn + c) * 16384;
        *(uint32_t*)(g_statein + baseb + soff) = pack2h(S0, S1);
        float f = expf(g_csum[(size_t)bh * NCn + c]);
        float2 st = *(const float2*)(g_states + basef + (size_t)p * Nn + np * 2);
        S0 = fmaf(f, S0, st.x);
        S1 = fmaf(f, S1, st.y);
    }
}

// ---------------- 7) Y_off via HMMA ----------------
#define KY_C   0
#define KY_S   16384
#define KY_EQ  32768
#define KY_SMEM 33280

__global__ __launch_bounds__(256) void k_yoff() {
    extern __shared__ unsigned char smy[];
    uint32_t sb = smem_u32(smy);
    float* Eq = (float*)(smy + KY_EQ);

    int c = blockIdx.x, h = blockIdx.y, b = blockIdx.z;
    int t = threadIdx.x, lane = t & 31, wid = t >> 5;
    size_t rowbase = ((size_t)(b * Ln + c * Qn)) * CONVD;
    size_t sbase_b = ((size_t)(b * Hn + h) * NCn + c) * 16384;

    for (int i = t; i < 64 * 64; i += 256) {
        int q = i >> 6, cp = i & 63;
        size_t g = rowbase + (size_t)q * CONVD + DINn + Nn + cp * 2;
        uint32_t cu = *(const uint32_t*)(g_xbc + g);
        int chunk = cp >> 5;
        uint32_t off = chunk * 8192 + swz128((uint32_t)(q * 128 + (cp & 31) * 4));
        *(uint32_t*)(smy + KY_C + off) = cu;
    }
    // S tile: raw copy of pre-swizzled fp16 image (16 KB)
    {
        const uint4* src = (const uint4*)(g_statein + sbase_b);
        uint4* dst = (uint4*)(smy + KY_S);
        #pragma unroll
        for (int i = 0; i < 4; i++) dst[t + i * 256] = src[t + i * 256];
    }
    if (t < Qn)
        Eq[t] = expf(g_acs[(size_t)(b * Ln + c * Qn + t) * Hn + h]);
    __syncthreads();

    int wq = wid & 3, ws = wid >> 2;
    int rA = wq * 16 + (lane & 7) + ((lane >> 3) & 1) * 8;
    int cA = ((lane >> 4) & 1) * 16;
    int rB = ws * 32 + (lane & 7) + ((lane >> 4) & 1) * 8;
    int cB = ((lane >> 3) & 1) * 16;

    float acc[4][4];
    #pragma unroll
    for (int i = 0; i < 4; i++)
        #pragma unroll
        for (int j = 0; j < 4; j++) acc[i][j] = 0.f;
    #pragma unroll
    for (int ch = 0; ch < 2; ch++) {
        #pragma unroll
        for (int k = 0; k < 4; k++) {
            uint32_t ah[4];
            LDSMX4(ah, sb + KY_C + ch * 8192 + swz128((uint32_t)(rA * 128 + k * 32 + cA)));
            uint32_t bh[2][4];
            #pragma unroll
            for (int ib = 0; ib < 2; ib++)
                LDSMX4(bh[ib], sb + KY_S + ch * 8192 +
                       swz128((uint32_t)((rB + ib * 16) * 128 + k * 32 + cB)));
            #pragma unroll
            for (int ib = 0; ib < 2; ib++)
                #pragma unroll
                for (int hf = 0; hf < 2; hf++)
                    MMA_FP16(acc[ib * 2 + hf], ah, bh[ib][2 * hf], bh[ib][2 * hf + 1]);
        }
    }
    int q0 = wq * 16 + (lane >> 2);
    int p0 = ws * 32 + (lane & 3) * 2;
    #pragma unroll
    for (int nt = 0; nt < 4; nt++) {
        int p = p0 + nt * 8;
        #pragma unroll
        for (int r2 = 0; r2 < 2; r2++) {
            int q = q0 + r2 * 8;
            float e = Eq[q];
            float* dst = g_y + ((size_t)(b * Ln + c * Qn + q) * Hn + h) * Pn + p;
            float2 cur = *(float2*)dst;
            cur.x += e * acc[nt][r2 * 2 + 0];
            cur.y += e * acc[nt][r2 * 2 + 1];
            *(float2*)dst = cur;
        }
    }
}

// ---------------- 8) gated rmsnorm -> fp16 A tiles ----------------
__global__ __launch_bounds__(256) void k_gatenorm_split(
    const float* __restrict__ gw, unsigned char* __restrict__ Af) {
    size_t row = blockIdx.x;
    int t = threadIdx.x;
    const float4* py = (const float4*)(g_y + row * DINn);
    const float4* pz = (const float4*)(g_proj + row * PROJW);
    float v[16];
    float ss = 0.f;
    #pragma unroll
    for (int i = 0; i < 4; i++) {
        float4 y4 = py[t * 4 + i];
        float4 z4 = pz[t * 4 + i];
        float x0 = y4.x * siluf(z4.x);
        float x1 = y4.y * siluf(z4.y);
        float x2 = y4.z * siluf(z4.z);
        float x3 = y4.w * siluf(z4.w);
        v[i * 4 + 0] = x0; v[i * 4 + 1] = x1; v[i * 4 + 2] = x2; v[i * 4 + 3] = x3;
        ss += x0 * x0 + x1 * x1 + x2 * x2 + x3 * x3;
    }
    float tot = block_reduce_sum(ss);
    float inv = rsqrtf(tot / (float)DINn + EPSf);
    int mt = (int)(row >> 7), r = (int)(row & 127);
    size_t tb = (size_t)mt * NCH2 * A_CH;
    #pragma unroll
    for (int j = 0; j < 8; j++) {
        int k = t * 16 + j * 2;
        uint32_t u = pack2h(v[j * 2] * inv * gw[k], v[j * 2 + 1] * inv * gw[k + 1]);
        int kc = k >> 6, cc = k & 63;
        size_t off = tb + (size_t)kc * A_CH + swz128((uint32_t)(r * 128 + cc * 2));
        *(uint32_t*)(Af + off) = u;
    }
}

// ---------------- launch ----------------
extern "C" void kernel_launch(void* const* d_in, const int* in_sizes, int n_in,
                              void* d_out, int out_size) {
    const float* hs   = (const float*)d_in[0];
    const float* res  = (const float*)d_in[1];
    const float* nw   = (const float*)d_in[2];
    const float* ipw  = (const float*)d_in[3];
    const float* cw   = (const float*)d_in[4];
    const float* cb   = (const float*)d_in[5];
    const float* alog = (const float*)d_in[6];
    const float* dtb  = (const float*)d_in[7];
    const float* dsk  = (const float*)d_in[8];
    const float* gnw  = (const float*)d_in[9];
    const float* opw  = (const float*)d_in[10];
    float* out = (float*)d_out;

    void *pproj, *pAf, *pBf, *pyfb;
    cudaGetSymbolAddress(&pproj, g_proj);
    cudaGetSymbolAddress(&pAf, g_Af);
    cudaGetSymbolAddress(&pBf, g_Bf);
    cudaGetSymbolAddress(&pyfb, g_y);

    float* resid_ptr = ((size_t)out_size >= 2ull * BLn * Dn)
                           ? out + (size_t)BLn * Dn
                           : (float*)pyfb;

    const int SMEM_GEMM = 1024 + NSTAGE * (16384 + 32768) + 64;
    cudaFuncSetAttribute(k_chunk, cudaFuncAttributeMaxDynamicSharedMemorySize, KC_SMEM);
    cudaFuncSetAttribute(k_yoff,  cudaFuncAttributeMaxDynamicSharedMemorySize, KY_SMEM);
    cudaFuncSetAttribute(gemm_mma_fp16, cudaFuncAttributeMaxDynamicSharedMemorySize, SMEM_GEMM);

    k_add_rmsnorm_split<<<BLn, 256>>>(hs, res, nw, resid_ptr, (unsigned char*)pAf);
    k_dtproj<<<BLn / 64, 256>>>(ipw, dtb, alog);

    {
        dim3 grid(PROJW / 32, Dn / 64);
        k_splitB<<<grid, 256>>>(ipw, (unsigned char*)pBf, PROJW, NCH1);
    }
    {
        dim3 grid(NT1, MTil);
        gemm_mma_fp16<<<grid, 512, SMEM_GEMM>>>(
            (const unsigned char*)pAf, (const unsigned char*)pBf,
            (float*)pproj, PROJW, NCH1);
    }

    k_conv2<<<Bn * 128 * 17, 256>>>(cw, cb);

    {
        dim3 grid(NCn, Hn, Bn);
        k_chunk<<<grid, 256, KC_SMEM>>>(dsk);
    }
    {
        dim3 grid(Bn * Hn, 16);
        k_scan<<<grid, 256>>>();
    }
    {
        dim3 grid(NCn, Hn, Bn);
        k_yoff<<<grid, 256, KY_SMEM>>>();
    }

    k_gatenorm_split<<<BLn, 256>>>(gnw, (unsigned char*)pAf);

    {
        dim3 grid(Dn / 32, DINn / 64);
        k_splitB<<<grid, 256>>>(opw, (unsigned char*)pBf, Dn, NCH2);
    }
    {
        dim3 grid(Dn / 256, MTil);
        gemm_mma_fp16<<<grid, 512, SMEM_GEMM>>>(
            (const unsigned char*)pAf, (const unsigned char*)pBf,
            out, Dn, NCH2);
    }
}